// round 9
// baseline (speedup 1.0000x reference)
#include <cuda_runtime.h>
#include <cuda_bf16.h>
#include <cuda_fp8.h>
#include <cstdint>

// Problem constants
#define B_  32
#define T_  64
#define M_  2048         // B*T
#define N_  16           // neighbors
#define E_  128
#define H_  128
#define G4_ 512          // 4*H
#define C_  100000
#define CP_ 100096       // padded rows = 782*128
#define K_  256          // UE + H
#define NEG 0.01f

// ---------------- scratch (device globals; no runtime alloc) ----------------
__device__ __align__(16) float g_spwT[E_*E_];       // [e][f]
__device__ __align__(16) float g_tpwT[E_*E_];
__device__ __align__(16) float g_spaWT[2*E_*E_];    // [c][f]
__device__ __align__(16) float g_tpaWT[2*E_*E_];
__device__ __align__(16) float g_WT [E_*G4_];       // [e][g]
__device__ __align__(16) float g_sWT[E_*G4_];
__device__ __align__(16) float g_tWT[E_*G4_];
__device__ __align__(16) float g_UT [E_*G4_];       // [e][g]
__device__ __align__(16) float g_spatial[M_*E_];
__device__ __align__(16) float g_temporal[M_*E_];
__device__ __align__(16) float g_preXST[M_*G4_];
__device__ __align__(16) float g_hout[M_*H_];
// GEMM operands:  hi pass (bf16, scaled x64 each side) and fp8 correction pass
__device__ __align__(16) __nv_bfloat16 g_Ahi[M_*K_];                 // bf16(A*64)
__device__ __align__(16) __nv_fp8_e4m3 g_A8 [M_*2*K_];               // [fp8(A) | fp8(Alo*4096)]
__device__ __align__(16) __nv_bfloat16 g_Bhi[(size_t)CP_*K_];        // bf16(B*64)
__device__ __align__(16) __nv_fp8_e4m3 g_B8 [(size_t)CP_*2*K_];      // [fp8(Blo*4096) | fp8(B)]

// ---------------- kernel 1: weight transposes ----------------
__global__ void prep_kernel(const float* __restrict__ sp_w, const float* __restrict__ sp_aW,
                            const float* __restrict__ tp_w, const float* __restrict__ tp_aW,
                            const float* __restrict__ W, const float* __restrict__ U,
                            const float* __restrict__ sW, const float* __restrict__ tW) {
    int i = blockIdx.x * blockDim.x + threadIdx.x;
    int stride = gridDim.x * blockDim.x;
    for (int j = i; j < E_*E_; j += stride) {
        int f = j >> 7, e = j & 127;
        g_spwT[e*E_ + f] = sp_w[j];
        g_tpwT[e*E_ + f] = tp_w[j];
    }
    for (int j = i; j < E_*2*E_; j += stride) {
        int f = j >> 8, c = j & 255;
        g_spaWT[c*E_ + f] = sp_aW[j];
        g_tpaWT[c*E_ + f] = tp_aW[j];
    }
    for (int j = i; j < G4_*E_; j += stride) {
        int g = j >> 7, e = j & 127;
        g_WT [e*G4_ + g] = W[j];
        g_sWT[e*G4_ + g] = sW[j];
        g_tWT[e*G4_ + g] = tW[j];
        g_UT [e*G4_ + g] = U[j];
    }
}

// ---------------- kernel 1b: split fuseW into bf16-hi (x64) + fp8 pieces --------
__global__ void convB_kernel(const float* __restrict__ fw) {
    size_t p = (size_t)blockIdx.x * blockDim.x + threadIdx.x;
    size_t tot = (size_t)CP_ * K_;
    size_t stride = (size_t)gridDim.x * blockDim.x;
    for (; p < tot; p += stride) {
        size_t r = p >> 8;
        int    k = (int)(p & 255);
        float v = (r < C_) ? fw[p] : 0.f;
        __nv_bfloat16 hi = __float2bfloat16(v);
        float lo = v - __bfloat162float(hi);
        g_Bhi[p] = __float2bfloat16(v * 64.f);
        g_B8[r*512 + k]       = __nv_fp8_e4m3(lo * 4096.f);
        g_B8[r*512 + 256 + k] = __nv_fp8_e4m3(v);
    }
}

// ---------------- kernel 2: GAT (spatial + temporal) ----------------
__global__ void gat_kernel(const int* __restrict__ x,
                           const int* __restrict__ sp_neigh, const int* __restrict__ tp_neigh,
                           const float* __restrict__ poi,
                           const float* __restrict__ sp_ab, const float* __restrict__ tp_ab) {
    int m = blockIdx.x;
    int which = blockIdx.y;
    int f = threadIdx.x;
    const int*   neigh  = which ? tp_neigh : sp_neigh;
    const float* wT     = which ? g_tpwT   : g_spwT;
    const float* aWT    = which ? g_tpaWT  : g_spaWT;
    const float* ab     = which ? tp_ab    : sp_ab;
    float*       outbuf = which ? g_temporal : g_spatial;

    __shared__ float nb[17][E_];
    __shared__ float px[E_];
    __shared__ float pn[N_][E_];

    {
        int ix = x[m];
        nb[16][f] = poi[ix*E_ + f];
        #pragma unroll
        for (int n = 0; n < N_; n++) {
            int idx = neigh[m*N_ + n];
            nb[n][f] = poi[idx*E_ + f];
        }
    }
    __syncthreads();

    float accx = 0.f;
    float accn[N_];
    #pragma unroll
    for (int n = 0; n < N_; n++) accn[n] = 0.f;
    for (int e = 0; e < E_; e++) {
        float wv = wT[e*E_ + f];
        accx += nb[16][e] * wv;
        #pragma unroll
        for (int n = 0; n < N_; n++) accn[n] += nb[n][e] * wv;
    }
    px[f] = accx;
    #pragma unroll
    for (int n = 0; n < N_; n++) pn[n][f] = accn[n];
    __syncthreads();

    float epx = 0.f;
    float ea[N_];
    #pragma unroll
    for (int n = 0; n < N_; n++) ea[n] = 0.f;
    for (int c = 0; c < E_; c++) {
        float a1 = aWT[c*E_ + f];
        float a2 = aWT[(E_ + c)*E_ + f];
        epx += px[c] * a1;
        #pragma unroll
        for (int n = 0; n < N_; n++) ea[n] += pn[n][c] * a2;
    }
    float abf = ab[f];
    float mx = -1e30f;
    #pragma unroll
    for (int n = 0; n < N_; n++) {
        float ev = epx + ea[n] + abf;
        ev = (ev >= 0.f) ? ev : NEG * ev;
        ea[n] = ev;
        mx = fmaxf(mx, ev);
    }
    float s = 0.f, o = 0.f;
    #pragma unroll
    for (int n = 0; n < N_; n++) {
        float p = expf(ea[n] - mx);
        s += p;
        o += p * pn[n][f];
    }
    outbuf[m*E_ + f] = o / s;
}

// ---------------- kernel 3: LSTM preactivation ----------------
// 256 threads: cg=tid&127 -> 4 gate-cols (float4), rh=tid>>7 -> 8 rows; 16 rows/block.
__global__ __launch_bounds__(256) void pre_kernel(const int* __restrict__ x,
                                                  const float* __restrict__ poi,
                                                  const float* __restrict__ Ub) {
    int tid = threadIdx.x;
    int cg = tid & 127;      // column group: cols 4cg..4cg+3
    int rh = tid >> 7;       // row half
    int m0 = blockIdx.x * 16;
    __shared__ float xs[16][3*E_];
    for (int i = tid; i < 16*3*E_; i += 256) {
        int r = i / (3*E_), e = i % (3*E_);
        int m = m0 + r;
        float v;
        if (e < E_)        v = poi[x[m]*E_ + e];
        else if (e < 2*E_) v = g_spatial[m*E_ + (e - E_)];
        else               v = g_temporal[m*E_ + (e - 2*E_)];
        xs[r][e] = v;
    }
    __syncthreads();

    const float4* W4  = reinterpret_cast<const float4*>(g_WT);
    const float4* sW4 = reinterpret_cast<const float4*>(g_sWT);
    const float4* tW4 = reinterpret_cast<const float4*>(g_tWT);
    float4 ub = reinterpret_cast<const float4*>(Ub)[cg];
    float4 acc[8];
    #pragma unroll
    for (int r = 0; r < 8; r++) acc[r] = ub;

    for (int e = 0; e < E_; e++) {
        float4 w1 = W4 [e*128 + cg];
        float4 w2 = sW4[e*128 + cg];
        float4 w3 = tW4[e*128 + cg];
        #pragma unroll
        for (int r = 0; r < 8; r++) {
            int row = rh*8 + r;
            float x1 = xs[row][e], x2 = xs[row][e + E_], x3 = xs[row][e + 2*E_];
            acc[r].x += x1*w1.x + x2*w2.x + x3*w3.x;
            acc[r].y += x1*w1.y + x2*w2.y + x3*w3.y;
            acc[r].z += x1*w1.z + x2*w2.z + x3*w3.z;
            acc[r].w += x1*w1.w + x2*w2.w + x3*w3.w;
        }
    }
    #pragma unroll
    for (int r = 0; r < 8; r++)
        reinterpret_cast<float4*>(g_preXST + (size_t)(m0 + rh*8 + r)*G4_)[cg] = acc[r];
}

// ---------------- kernel 4: sequential LSTM, 256 threads, float2 U loads --------
__global__ __launch_bounds__(256) void lstm_kernel() {
    int b = blockIdx.x;
    int tid = threadIdx.x;          // handles gate-cols 2tid, 2tid+1
    __shared__ float hs[H_];
    __shared__ float gsm[G4_];
    float c = 0.f;
    if (tid < H_) hs[tid] = 0.f;
    __syncthreads();
    const float2* U2 = reinterpret_cast<const float2*>(g_UT);
    for (int t = 0; t < T_; t++) {
        int m = b*T_ + t;
        float2 a = reinterpret_cast<const float2*>(g_preXST + (size_t)m*G4_)[tid];
        #pragma unroll 8
        for (int e = 0; e < E_; e++) {
            float h = hs[e];
            float2 u = U2[e*256 + tid];
            a.x += h*u.x; a.y += h*u.y;
        }
        gsm[2*tid]   = a.x;
        gsm[2*tid+1] = a.y;
        __syncthreads();
        if (tid < H_) {
            float ig = 1.f / (1.f + expf(-gsm[tid]));
            float fg = 1.f / (1.f + expf(-gsm[H_ + tid]));
            float og = 1.f / (1.f + expf(-gsm[2*H_ + tid]));
            float gg = tanhf(gsm[3*H_ + tid]);
            c = fg*c + ig*gg;
            float h = og * tanhf(c);
            hs[tid] = h;
            g_hout[m*H_ + tid] = h;
        }
        __syncthreads();
    }
}

// ---------------- kernel 5: concat + operand split of A ----------------
__global__ void fuse_kernel(const int* __restrict__ users, const float* __restrict__ user_table) {
    int m = blockIdx.x;
    int k = threadIdx.x;
    int u = users[m];
    float v = (k < 128) ? user_table[u*128 + k] : g_hout[m*H_ + (k - 128)];
    __nv_bfloat16 hi = __float2bfloat16(v);
    float lo = v - __bfloat162float(hi);
    g_Ahi[m*K_ + k] = __float2bfloat16(v * 64.f);
    g_A8[m*512 + k]       = __nv_fp8_e4m3(v);
    g_A8[m*512 + 256 + k] = __nv_fp8_e4m3(lo * 4096.f);
}

// ---------------- kernel 6: head GEMM  (bf16 hi-pass + fp8 correction pass) -----
// CTA tile 128x128, 8 warps (2x4), warp tile 64x32.
// 16 chunks x 64B/row: kc 0..7  = bf16 hi*hi (BK=32 bf16)
//                      kc 8..15 = fp8  [A|Alo]*[Blo|B] (BK=64 fp8)
// Accumulators share scale 2^12; epilogue multiplies by 2^-12.
#define ROWB 40              // smem row stride in uint16 units (80 bytes)
#define NKCH 16

__device__ __forceinline__ void cpa16s(uint32_t dst, const void* src) {
    asm volatile("cp.async.cg.shared.global [%0], [%1], 16;" :: "r"(dst), "l"(src));
}
__device__ __forceinline__ void ldsm4(uint32_t* r, uint32_t addr) {
    asm volatile("ldmatrix.sync.aligned.m8n8.x4.shared.b16 {%0,%1,%2,%3}, [%4];"
                 : "=r"(r[0]), "=r"(r[1]), "=r"(r[2]), "=r"(r[3]) : "r"(addr));
}
__device__ __forceinline__ void mma16816(float* c, const uint32_t* a, uint32_t b0, uint32_t b1) {
    asm volatile("mma.sync.aligned.m16n8k16.row.col.f32.bf16.bf16.f32 "
                 "{%0,%1,%2,%3}, {%4,%5,%6,%7}, {%8,%9}, {%0,%1,%2,%3};"
                 : "+f"(c[0]), "+f"(c[1]), "+f"(c[2]), "+f"(c[3])
                 : "r"(a[0]), "r"(a[1]), "r"(a[2]), "r"(a[3]), "r"(b0), "r"(b1));
}
__device__ __forceinline__ void mma16832f8(float* c, const uint32_t* a, uint32_t b0, uint32_t b1) {
    asm volatile("mma.sync.aligned.m16n8k32.row.col.f32.e4m3.e4m3.f32 "
                 "{%0,%1,%2,%3}, {%4,%5,%6,%7}, {%8,%9}, {%0,%1,%2,%3};"
                 : "+f"(c[0]), "+f"(c[1]), "+f"(c[2]), "+f"(c[3])
                 : "r"(a[0]), "r"(a[1]), "r"(a[2]), "r"(a[3]), "r"(b0), "r"(b1));
}

__global__ __launch_bounds__(256, 2) void gemm_mma_kernel(const float* __restrict__ bias,
                                                          float* __restrict__ out) {
    __shared__ __align__(16) uint16_t sA[2][128*ROWB];
    __shared__ __align__(16) uint16_t sB[2][128*ROWB];
    int tid = threadIdx.x;
    int wid = tid >> 5, lane = tid & 31;
    int wm = wid >> 2, wn = wid & 3;
    int m0 = blockIdx.x * 128;
    int n0 = blockIdx.y * 128;

    float acc[16][4];
    #pragma unroll
    for (int i = 0; i < 16; i++)
        #pragma unroll
        for (int q = 0; q < 4; q++) acc[i][q] = 0.f;

    uint32_t sA_u[2], sB_u[2];
    sA_u[0] = (uint32_t)__cvta_generic_to_shared(sA[0]);
    sA_u[1] = (uint32_t)__cvta_generic_to_shared(sA[1]);
    sB_u[0] = (uint32_t)__cvta_generic_to_shared(sB[0]);
    sB_u[1] = (uint32_t)__cvta_generic_to_shared(sB[1]);

    // loader: every chunk moves 64B per row for A(128 rows) and B(128 rows).
    // Row stride in gmem is 512 bytes for both bf16 (256*2) and fp8 (512*1) operands.
    auto load_chunk = [&](int kc, int stg) {
        const char* Asrc;
        const char* Bsrc;
        if (kc < 8) { Asrc = (const char*)g_Ahi; Bsrc = (const char*)g_Bhi; }
        else        { Asrc = (const char*)g_A8;  Bsrc = (const char*)g_B8;  }
        int chb = (kc & 7) * 64;          // byte offset inside the row
        #pragma unroll
        for (int it = 0; it < 2; it++) {
            int i = tid + it*256;          // 0..511
            int r = i >> 2, gc = i & 3;    // row, 16B granule
            uint32_t soff = (uint32_t)(r*80 + gc*16);
            cpa16s(sA_u[stg] + soff, Asrc + (size_t)(m0 + r)*512 + chb + gc*16);
            cpa16s(sB_u[stg] + soff, Bsrc + (size_t)(n0 + r)*512 + chb + gc*16);
        }
        asm volatile("cp.async.commit_group;" ::: "memory");
    };

    load_chunk(0, 0);

    int rowsel = lane & 7;
    int mat01 = (lane >> 3) & 1;
    int mat23 = (lane >> 4);

    for (int kc = 0; kc < NKCH; kc++) {
        int stg = kc & 1;
        if (kc + 1 < NKCH) {
            load_chunk(kc + 1, (kc + 1) & 1);
            asm volatile("cp.async.wait_group 1;" ::: "memory");
        } else {
            asm volatile("cp.async.wait_group 0;" ::: "memory");
        }
        __syncthreads();

        #pragma unroll
        for (int s = 0; s < 2; s++) {
            int colb = s*16 + mat23*8;
            uint32_t afr[4][4];
            #pragma unroll
            for (int im = 0; im < 4; im++) {
                int row = wm*64 + im*16 + mat01*8 + rowsel;
                ldsm4(afr[im], sA_u[stg] + (uint32_t)(row*ROWB + colb)*2u);
            }
            uint32_t bfr[2][4];
            #pragma unroll
            for (int j2 = 0; j2 < 2; j2++) {
                int row = wn*32 + j2*16 + mat01*8 + rowsel;
                ldsm4(bfr[j2], sB_u[stg] + (uint32_t)(row*ROWB + colb)*2u);
            }
            if (kc < 8) {
                #pragma unroll
                for (int im = 0; im < 4; im++)
                    #pragma unroll
                    for (int jn = 0; jn < 4; jn++) {
                        int h = jn & 1;
                        mma16816(acc[im*4 + jn], afr[im], bfr[jn>>1][h], bfr[jn>>1][h + 2]);
                    }
            } else {
                #pragma unroll
                for (int im = 0; im < 4; im++)
                    #pragma unroll
                    for (int jn = 0; jn < 4; jn++) {
                        int h = jn & 1;
                        mma16832f8(acc[im*4 + jn], afr[im], bfr[jn>>1][h], bfr[jn>>1][h + 2]);
                    }
            }
        }
        __syncthreads();
    }

    // epilogue (x 2^-12): c0=(g,2t) c1=(g,2t+1) c2=(g+8,2t) c3=(g+8,2t+1)
    const float SCL = 1.f / 4096.f;
    int g = lane >> 2, t = lane & 3;
    #pragma unroll
    for (int im = 0; im < 4; im++) {
        int row = m0 + wm*64 + im*16 + g;
        size_t r0 = (size_t)row * C_;
        #pragma unroll
        for (int jn = 0; jn < 4; jn++) {
            int col = n0 + wn*32 + jn*8 + 2*t;
            if (col < C_) {
                float2 bv = *reinterpret_cast<const float2*>(bias + col);
                const float* a = acc[im*4 + jn];
                float2 v0 = make_float2(a[0]*SCL + bv.x, a[1]*SCL + bv.y);
                float2 v1 = make_float2(a[2]*SCL + bv.x, a[3]*SCL + bv.y);
                *reinterpret_cast<float2*>(out + r0 + col) = v0;
                *reinterpret_cast<float2*>(out + r0 + (size_t)8*C_ + col) = v1;
            }
        }
    }
}

// ---------------- launch ----------------
extern "C" void kernel_launch(void* const* d_in, const int* in_sizes, int n_in,
                              void* d_out, int out_size) {
    const int*   x       = (const int*)  d_in[0];
    const int*   users   = (const int*)  d_in[1];
    const int*   spn     = (const int*)  d_in[2];
    const int*   tpn     = (const int*)  d_in[3];
    const float* poi     = (const float*)d_in[4];
    const float* usert   = (const float*)d_in[5];
    const float* sp_w    = (const float*)d_in[6];
    const float* sp_aW   = (const float*)d_in[7];
    const float* sp_ab   = (const float*)d_in[8];
    const float* tp_w    = (const float*)d_in[9];
    const float* tp_aW   = (const float*)d_in[10];
    const float* tp_ab   = (const float*)d_in[11];
    const float* W       = (const float*)d_in[12];
    const float* U       = (const float*)d_in[13];
    const float* Ub      = (const float*)d_in[14];
    const float* sW      = (const float*)d_in[15];
    const float* tW      = (const float*)d_in[16];
    const float* fuseW   = (const float*)d_in[17];
    const float* fuseb   = (const float*)d_in[18];
    float* out = (float*)d_out;

    prep_kernel<<<256, 256>>>(sp_w, sp_aW, tp_w, tp_aW, W, U, sW, tW);
    convB_kernel<<<8192, 256>>>(fuseW);
    gat_kernel<<<dim3(M_, 2), 128>>>(x, spn, tpn, poi, sp_ab, tp_ab);
    pre_kernel<<<M_/16, 256>>>(x, poi, Ub);
    lstm_kernel<<<B_, 256>>>();
    fuse_kernel<<<M_, 256>>>(users, usert);
    gemm_mma_kernel<<<dim3(M_/128, CP_/128), 256>>>(fuseb, out);
}

// round 11
// speedup vs baseline: 1.4693x; 1.4693x over previous
#include <cuda_runtime.h>
#include <cuda_bf16.h>
#include <cuda_fp16.h>
#include <cstdint>

// Problem constants
#define B_  32
#define T_  64
#define M_  2048         // B*T
#define N_  16           // neighbors
#define E_  128
#define H_  128
#define G4_ 512          // 4*H
#define C_  100000
#define CP_ 100096       // padded rows = 782*128
#define K_  256          // UE + H
#define NEG 0.01f

// ---------------- scratch (device globals; no runtime alloc) ----------------
__device__ __align__(16) float g_spwT[E_*E_];       // [e][f]
__device__ __align__(16) float g_tpwT[E_*E_];
__device__ __align__(16) float g_spaWT[2*E_*E_];    // [c][f]
__device__ __align__(16) float g_tpaWT[2*E_*E_];
__device__ __align__(16) float g_WT [E_*G4_];       // [e][g]
__device__ __align__(16) float g_sWT[E_*G4_];
__device__ __align__(16) float g_tWT[E_*G4_];
__device__ __align__(16) __half g_U16[E_*G4_];      // [e][g] fp16 recurrent weights
__device__ __align__(16) float g_spatial[M_*E_];
__device__ __align__(16) float g_temporal[M_*E_];
__device__ __align__(16) float g_preXST[M_*G4_];
__device__ __align__(16) float g_hout[M_*H_];
// GEMM operands (fp16 two-pass split, shared accumulator scale 2^11)
__device__ __align__(16) __half g_Ah [M_*K_];                 // fp16(A)
__device__ __align__(16) __half g_Bh2[(size_t)CP_*K_];        // fp16(B) * 2048
__device__ __align__(16) __half g_Bl2[(size_t)CP_*K_];        // fp16((B - fp16(B)) * 2048)

// ---------------- kernel 1: weight transposes ----------------
__global__ void prep_kernel(const float* __restrict__ sp_w, const float* __restrict__ sp_aW,
                            const float* __restrict__ tp_w, const float* __restrict__ tp_aW,
                            const float* __restrict__ W, const float* __restrict__ U,
                            const float* __restrict__ sW, const float* __restrict__ tW) {
    int i = blockIdx.x * blockDim.x + threadIdx.x;
    int stride = gridDim.x * blockDim.x;
    for (int j = i; j < E_*E_; j += stride) {
        int f = j >> 7, e = j & 127;
        g_spwT[e*E_ + f] = sp_w[j];
        g_tpwT[e*E_ + f] = tp_w[j];
    }
    for (int j = i; j < E_*2*E_; j += stride) {
        int f = j >> 8, c = j & 255;
        g_spaWT[c*E_ + f] = sp_aW[j];
        g_tpaWT[c*E_ + f] = tp_aW[j];
    }
    for (int j = i; j < G4_*E_; j += stride) {
        int g = j >> 7, e = j & 127;
        g_WT [e*G4_ + g] = W[j];
        g_sWT[e*G4_ + g] = sW[j];
        g_tWT[e*G4_ + g] = tW[j];
        g_U16[e*G4_ + g] = __float2half(U[j]);
    }
}

// ---------------- kernel 1b: split fuseW into fp16 hi(x2048) + lo(x2048) --------
__global__ void convB_kernel(const float* __restrict__ fw) {
    size_t p = (size_t)blockIdx.x * blockDim.x + threadIdx.x;
    size_t tot = (size_t)CP_ * K_;
    size_t stride = (size_t)gridDim.x * blockDim.x;
    for (; p < tot; p += stride) {
        size_t r = p >> 8;
        float v = (r < C_) ? fw[p] : 0.f;
        __half h = __float2half(v);
        float hf = __half2float(h);
        g_Bh2[p] = __float2half(hf * 2048.f);           // exact pow2 scale of an fp16 value
        g_Bl2[p] = __float2half((v - hf) * 2048.f);
    }
}

// ---------------- kernel 2: GAT (spatial + temporal) ----------------
__global__ void gat_kernel(const int* __restrict__ x,
                           const int* __restrict__ sp_neigh, const int* __restrict__ tp_neigh,
                           const float* __restrict__ poi,
                           const float* __restrict__ sp_ab, const float* __restrict__ tp_ab) {
    int m = blockIdx.x;
    int which = blockIdx.y;
    int f = threadIdx.x;
    const int*   neigh  = which ? tp_neigh : sp_neigh;
    const float* wT     = which ? g_tpwT   : g_spwT;
    const float* aWT    = which ? g_tpaWT  : g_spaWT;
    const float* ab     = which ? tp_ab    : sp_ab;
    float*       outbuf = which ? g_temporal : g_spatial;

    __shared__ float nb[17][E_];
    __shared__ float px[E_];
    __shared__ float pn[N_][E_];

    {
        int ix = x[m];
        nb[16][f] = poi[ix*E_ + f];
        #pragma unroll
        for (int n = 0; n < N_; n++) {
            int idx = neigh[m*N_ + n];
            nb[n][f] = poi[idx*E_ + f];
        }
    }
    __syncthreads();

    float accx = 0.f;
    float accn[N_];
    #pragma unroll
    for (int n = 0; n < N_; n++) accn[n] = 0.f;
    for (int e = 0; e < E_; e++) {
        float wv = wT[e*E_ + f];
        accx += nb[16][e] * wv;
        #pragma unroll
        for (int n = 0; n < N_; n++) accn[n] += nb[n][e] * wv;
    }
    px[f] = accx;
    #pragma unroll
    for (int n = 0; n < N_; n++) pn[n][f] = accn[n];
    __syncthreads();

    float epx = 0.f;
    float ea[N_];
    #pragma unroll
    for (int n = 0; n < N_; n++) ea[n] = 0.f;
    for (int c = 0; c < E_; c++) {
        float a1 = aWT[c*E_ + f];
        float a2 = aWT[(E_ + c)*E_ + f];
        epx += px[c] * a1;
        #pragma unroll
        for (int n = 0; n < N_; n++) ea[n] += pn[n][c] * a2;
    }
    float abf = ab[f];
    float mx = -1e30f;
    #pragma unroll
    for (int n = 0; n < N_; n++) {
        float ev = epx + ea[n] + abf;
        ev = (ev >= 0.f) ? ev : NEG * ev;
        ea[n] = ev;
        mx = fmaxf(mx, ev);
    }
    float s = 0.f, o = 0.f;
    #pragma unroll
    for (int n = 0; n < N_; n++) {
        float p = expf(ea[n] - mx);
        s += p;
        o += p * pn[n][f];
    }
    outbuf[m*E_ + f] = o / s;
}

// ---------------- kernel 3: LSTM preactivation ----------------
// 256 threads, 8 rows/block (256 blocks): cg=tid&127 -> 4 gate-cols, rh=tid>>7 -> 4 rows.
__global__ __launch_bounds__(256) void pre_kernel(const int* __restrict__ x,
                                                  const float* __restrict__ poi,
                                                  const float* __restrict__ Ub) {
    int tid = threadIdx.x;
    int cg = tid & 127;
    int rh = tid >> 7;
    int m0 = blockIdx.x * 8;
    __shared__ float xs[8][3*E_];
    for (int i = tid; i < 8*3*E_; i += 256) {
        int r = i / (3*E_), e = i % (3*E_);
        int m = m0 + r;
        float v;
        if (e < E_)        v = poi[x[m]*E_ + e];
        else if (e < 2*E_) v = g_spatial[m*E_ + (e - E_)];
        else               v = g_temporal[m*E_ + (e - 2*E_)];
        xs[r][e] = v;
    }
    __syncthreads();

    const float4* W4  = reinterpret_cast<const float4*>(g_WT);
    const float4* sW4 = reinterpret_cast<const float4*>(g_sWT);
    const float4* tW4 = reinterpret_cast<const float4*>(g_tWT);
    float4 ub = reinterpret_cast<const float4*>(Ub)[cg];
    float4 acc[4];
    #pragma unroll
    for (int r = 0; r < 4; r++) acc[r] = ub;

    for (int e = 0; e < E_; e++) {
        float4 w1 = W4 [e*128 + cg];
        float4 w2 = sW4[e*128 + cg];
        float4 w3 = tW4[e*128 + cg];
        #pragma unroll
        for (int r = 0; r < 4; r++) {
            int row = rh*4 + r;
            float x1 = xs[row][e], x2 = xs[row][e + E_], x3 = xs[row][e + 2*E_];
            acc[r].x += x1*w1.x + x2*w2.x + x3*w3.x;
            acc[r].y += x1*w1.y + x2*w2.y + x3*w3.y;
            acc[r].z += x1*w1.z + x2*w2.z + x3*w3.z;
            acc[r].w += x1*w1.w + x2*w2.w + x3*w3.w;
        }
    }
    #pragma unroll
    for (int r = 0; r < 4; r++)
        reinterpret_cast<float4*>(g_preXST + (size_t)(m0 + rh*4 + r)*G4_)[cg] = acc[r];
}

// ---------------- kernel 4: sequential LSTM, 256 threads, fp16 U (half2 loads) --
__global__ __launch_bounds__(256) void lstm_kernel() {
    int b = blockIdx.x;
    int tid = threadIdx.x;          // handles gate-cols 2tid, 2tid+1
    __shared__ float hs[H_];
    __shared__ float gsm[G4_];
    float c = 0.f;
    if (tid < H_) hs[tid] = 0.f;
    __syncthreads();
    const __half2* U2 = reinterpret_cast<const __half2*>(g_U16);
    for (int t = 0; t < T_; t++) {
        int m = b*T_ + t;
        float2 a = reinterpret_cast<const float2*>(g_preXST + (size_t)m*G4_)[tid];
        #pragma unroll 8
        for (int e = 0; e < E_; e++) {
            float h = hs[e];
            float2 u = __half22float2(U2[e*256 + tid]);
            a.x += h*u.x; a.y += h*u.y;
        }
        gsm[2*tid]   = a.x;
        gsm[2*tid+1] = a.y;
        __syncthreads();
        if (tid < H_) {
            float ig = 1.f / (1.f + expf(-gsm[tid]));
            float fg = 1.f / (1.f + expf(-gsm[H_ + tid]));
            float og = 1.f / (1.f + expf(-gsm[2*H_ + tid]));
            float gg = tanhf(gsm[3*H_ + tid]);
            c = fg*c + ig*gg;
            float h = og * tanhf(c);
            hs[tid] = h;
            g_hout[m*H_ + tid] = h;
        }
        __syncthreads();
    }
}

// ---------------- kernel 5: concat + fp16 A ----------------
__global__ void fuse_kernel(const int* __restrict__ users, const float* __restrict__ user_table) {
    int m = blockIdx.x;
    int k = threadIdx.x;
    int u = users[m];
    float v = (k < 128) ? user_table[u*128 + k] : g_hout[m*H_ + (k - 128)];
    g_Ah[m*K_ + k] = __float2half(v);
}

// ---------------- kernel 6: head GEMM  (fp16 two-pass) ----------------
// CTA tile 128x128, 8 warps (2x4), warp tile 64x32, BK=32, double-buffered cp.async.
// 16 chunks: kc 0..7  = Ah * Bh2   (fp16(A) * fp16(B)*2^11)
//            kc 8..15 = Ah * Bl2   (fp16(A) * lo(B)*2^11)
// Shared accumulator scale 2^11; epilogue multiplies by 2^-11.
#define ROWB 40              // smem row stride in uint16 units (80 bytes)
#define NKCH 16

__device__ __forceinline__ void cpa16s(uint32_t dst, const void* src) {
    asm volatile("cp.async.cg.shared.global [%0], [%1], 16;" :: "r"(dst), "l"(src));
}
__device__ __forceinline__ void ldsm4(uint32_t* r, uint32_t addr) {
    asm volatile("ldmatrix.sync.aligned.m8n8.x4.shared.b16 {%0,%1,%2,%3}, [%4];"
                 : "=r"(r[0]), "=r"(r[1]), "=r"(r[2]), "=r"(r[3]) : "r"(addr));
}
__device__ __forceinline__ void mma16816h(float* c, const uint32_t* a, uint32_t b0, uint32_t b1) {
    asm volatile("mma.sync.aligned.m16n8k16.row.col.f32.f16.f16.f32 "
                 "{%0,%1,%2,%3}, {%4,%5,%6,%7}, {%8,%9}, {%0,%1,%2,%3};"
                 : "+f"(c[0]), "+f"(c[1]), "+f"(c[2]), "+f"(c[3])
                 : "r"(a[0]), "r"(a[1]), "r"(a[2]), "r"(a[3]), "r"(b0), "r"(b1));
}

__global__ __launch_bounds__(256, 2) void gemm_mma_kernel(const float* __restrict__ bias,
                                                          float* __restrict__ out) {
    __shared__ __align__(16) uint16_t sA[2][128*ROWB];
    __shared__ __align__(16) uint16_t sB[2][128*ROWB];
    int tid = threadIdx.x;
    int wid = tid >> 5, lane = tid & 31;
    int wm = wid >> 2, wn = wid & 3;
    int m0 = blockIdx.x * 128;
    int n0 = blockIdx.y * 128;

    float acc[16][4];
    #pragma unroll
    for (int i = 0; i < 16; i++)
        #pragma unroll
        for (int q = 0; q < 4; q++) acc[i][q] = 0.f;

    uint32_t sA_u[2], sB_u[2];
    sA_u[0] = (uint32_t)__cvta_generic_to_shared(sA[0]);
    sA_u[1] = (uint32_t)__cvta_generic_to_shared(sA[1]);
    sB_u[0] = (uint32_t)__cvta_generic_to_shared(sB[0]);
    sB_u[1] = (uint32_t)__cvta_generic_to_shared(sB[1]);

    // loader: 64B per row per chunk for A(128 rows) + B(128 rows); gmem row = 512B.
    auto load_chunk = [&](int kc, int stg) {
        const char* Bsrc = (kc < 8) ? (const char*)g_Bh2 : (const char*)g_Bl2;
        const char* Asrc = (const char*)g_Ah;
        int chb = (kc & 7) * 64;
        #pragma unroll
        for (int it = 0; it < 2; it++) {
            int i = tid + it*256;          // 0..511
            int r = i >> 2, gc = i & 3;    // row, 16B granule
            uint32_t soff = (uint32_t)(r*80 + gc*16);
            cpa16s(sA_u[stg] + soff, Asrc + (size_t)(m0 + r)*512 + chb + gc*16);
            cpa16s(sB_u[stg] + soff, Bsrc + (size_t)(n0 + r)*512 + chb + gc*16);
        }
        asm volatile("cp.async.commit_group;" ::: "memory");
    };

    load_chunk(0, 0);

    int rowsel = lane & 7;
    int mat01 = (lane >> 3) & 1;
    int mat23 = (lane >> 4);

    for (int kc = 0; kc < NKCH; kc++) {
        int stg = kc & 1;
        if (kc + 1 < NKCH) {
            load_chunk(kc + 1, (kc + 1) & 1);
            asm volatile("cp.async.wait_group 1;" ::: "memory");
        } else {
            asm volatile("cp.async.wait_group 0;" ::: "memory");
        }
        __syncthreads();

        #pragma unroll
        for (int s = 0; s < 2; s++) {
            int colb = s*16 + mat23*8;
            uint32_t afr[4][4];
            #pragma unroll
            for (int im = 0; im < 4; im++) {
                int row = wm*64 + im*16 + mat01*8 + rowsel;
                ldsm4(afr[im], sA_u[stg] + (uint32_t)(row*ROWB + colb)*2u);
            }
            uint32_t bfr[2][4];
            #pragma unroll
            for (int j2 = 0; j2 < 2; j2++) {
                int row = wn*32 + j2*16 + mat01*8 + rowsel;
                ldsm4(bfr[j2], sB_u[stg] + (uint32_t)(row*ROWB + colb)*2u);
            }
            #pragma unroll
            for (int im = 0; im < 4; im++)
                #pragma unroll
                for (int jn = 0; jn < 4; jn++) {
                    int h = jn & 1;
                    mma16816h(acc[im*4 + jn], afr[im], bfr[jn>>1][h], bfr[jn>>1][h + 2]);
                }
        }
        __syncthreads();
    }

    // epilogue (x 2^-11): c0=(g,2t) c1=(g,2t+1) c2=(g+8,2t) c3=(g+8,2t+1)
    const float SCL = 1.f / 2048.f;
    int g = lane >> 2, t = lane & 3;
    #pragma unroll
    for (int im = 0; im < 4; im++) {
        int row = m0 + wm*64 + im*16 + g;
        size_t r0 = (size_t)row * C_;
        #pragma unroll
        for (int jn = 0; jn < 4; jn++) {
            int col = n0 + wn*32 + jn*8 + 2*t;
            if (col < C_) {
                float2 bv = *reinterpret_cast<const float2*>(bias + col);
                const float* a = acc[im*4 + jn];
                float2 v0 = make_float2(a[0]*SCL + bv.x, a[1]*SCL + bv.y);
                float2 v1 = make_float2(a[2]*SCL + bv.x, a[3]*SCL + bv.y);
                *reinterpret_cast<float2*>(out + r0 + col) = v0;
                *reinterpret_cast<float2*>(out + r0 + (size_t)8*C_ + col) = v1;
            }
        }
    }
}

// ---------------- launch ----------------
extern "C" void kernel_launch(void* const* d_in, const int* in_sizes, int n_in,
                              void* d_out, int out_size) {
    const int*   x       = (const int*)  d_in[0];
    const int*   users   = (const int*)  d_in[1];
    const int*   spn     = (const int*)  d_in[2];
    const int*   tpn     = (const int*)  d_in[3];
    const float* poi     = (const float*)d_in[4];
    const float* usert   = (const float*)d_in[5];
    const float* sp_w    = (const float*)d_in[6];
    const float* sp_aW   = (const float*)d_in[7];
    const float* sp_ab   = (const float*)d_in[8];
    const float* tp_w    = (const float*)d_in[9];
    const float* tp_aW   = (const float*)d_in[10];
    const float* tp_ab   = (const float*)d_in[11];
    const float* W       = (const float*)d_in[12];
    const float* U       = (const float*)d_in[13];
    const float* Ub      = (const float*)d_in[14];
    const float* sW      = (const float*)d_in[15];
    const float* tW      = (const float*)d_in[16];
    const float* fuseW   = (const float*)d_in[17];
    const float* fuseb   = (const float*)d_in[18];
    float* out = (float*)d_out;

    prep_kernel<<<256, 256>>>(sp_w, sp_aW, tp_w, tp_aW, W, U, sW, tW);
    convB_kernel<<<8192, 256>>>(fuseW);
    gat_kernel<<<dim3(M_, 2), 128>>>(x, spn, tpn, poi, sp_ab, tp_ab);
    pre_kernel<<<M_/8, 256>>>(x, poi, Ub);
    lstm_kernel<<<B_, 256>>>();
    fuse_kernel<<<M_, 256>>>(users, usert);
    gemm_mma_kernel<<<dim3(M_/128, CP_/128), 256>>>(fuseb, out);
}

// round 12
// speedup vs baseline: 2.0857x; 1.4194x over previous
#include <cuda_runtime.h>
#include <cuda_bf16.h>
#include <cuda_fp16.h>
#include <cstdint>

// Problem constants
#define B_  32
#define T_  64
#define M_  2048         // B*T
#define N_  16           // neighbors
#define E_  128
#define H_  128
#define G4_ 512          // 4*H
#define C_  100000
#define CP_ 100096       // padded rows = 782*128
#define K_  256          // UE + H
#define NEG 0.01f

// ---------------- scratch (device globals; no runtime alloc) ----------------
__device__ __align__(16) float g_spwT[E_*E_];       // [e][f]
__device__ __align__(16) float g_tpwT[E_*E_];
__device__ __align__(16) float g_spaWT[2*E_*E_];    // [c][f]
__device__ __align__(16) float g_tpaWT[2*E_*E_];
__device__ __align__(16) __half g_W16 [E_*G4_];     // [e][g] fp16 x-path weights
__device__ __align__(16) __half g_sW16[E_*G4_];
__device__ __align__(16) __half g_tW16[E_*G4_];
__device__ __align__(16) __half g_U16[E_*G4_];      // [e][g] fp16 recurrent weights
__device__ __align__(16) float g_spatial[M_*E_];
__device__ __align__(16) float g_temporal[M_*E_];
__device__ __align__(16) float g_preXST[M_*G4_];
__device__ __align__(16) float g_hout[M_*H_];
// GEMM operands (single-pass fp16)
__device__ __align__(16) __half g_Ah[M_*K_];                  // fp16(A)
__device__ __align__(16) __half g_Bh[(size_t)CP_*K_];         // fp16(B)

// ---------------- kernel 1: weight transposes ----------------
__global__ void prep_kernel(const float* __restrict__ sp_w, const float* __restrict__ sp_aW,
                            const float* __restrict__ tp_w, const float* __restrict__ tp_aW,
                            const float* __restrict__ W, const float* __restrict__ U,
                            const float* __restrict__ sW, const float* __restrict__ tW) {
    int i = blockIdx.x * blockDim.x + threadIdx.x;
    int stride = gridDim.x * blockDim.x;
    for (int j = i; j < E_*E_; j += stride) {
        int f = j >> 7, e = j & 127;
        g_spwT[e*E_ + f] = sp_w[j];
        g_tpwT[e*E_ + f] = tp_w[j];
    }
    for (int j = i; j < E_*2*E_; j += stride) {
        int f = j >> 8, c = j & 255;
        g_spaWT[c*E_ + f] = sp_aW[j];
        g_tpaWT[c*E_ + f] = tp_aW[j];
    }
    for (int j = i; j < G4_*E_; j += stride) {
        int g = j >> 7, e = j & 127;
        g_W16 [e*G4_ + g] = __float2half(W[j]);
        g_sW16[e*G4_ + g] = __float2half(sW[j]);
        g_tW16[e*G4_ + g] = __float2half(tW[j]);
        g_U16 [e*G4_ + g] = __float2half(U[j]);
    }
}

// ---------------- kernel 1b: fuseW -> fp16 (padded) ----------------
__global__ void convB_kernel(const float* __restrict__ fw) {
    size_t p2 = (size_t)blockIdx.x * blockDim.x + threadIdx.x;
    size_t tot = (size_t)CP_ * K_ / 2;
    size_t stride = (size_t)gridDim.x * blockDim.x;
    for (; p2 < tot; p2 += stride) {
        size_t p = p2 * 2;
        size_t r = p >> 8;
        float2 v = make_float2(0.f, 0.f);
        if (r < C_) v = *reinterpret_cast<const float2*>(fw + p);
        __half2 h;
        h.x = __float2half(v.x);
        h.y = __float2half(v.y);
        reinterpret_cast<__half2*>(g_Bh)[p2] = h;
    }
}

// ---------------- kernel 2: GAT (spatial + temporal) ----------------
__global__ void gat_kernel(const int* __restrict__ x,
                           const int* __restrict__ sp_neigh, const int* __restrict__ tp_neigh,
                           const float* __restrict__ poi,
                           const float* __restrict__ sp_ab, const float* __restrict__ tp_ab) {
    int m = blockIdx.x;
    int which = blockIdx.y;
    int f = threadIdx.x;
    const int*   neigh  = which ? tp_neigh : sp_neigh;
    const float* wT     = which ? g_tpwT   : g_spwT;
    const float* aWT    = which ? g_tpaWT  : g_spaWT;
    const float* ab     = which ? tp_ab    : sp_ab;
    float*       outbuf = which ? g_temporal : g_spatial;

    __shared__ float nb[17][E_];
    __shared__ float px[E_];
    __shared__ float pn[N_][E_];

    {
        int ix = x[m];
        nb[16][f] = poi[ix*E_ + f];
        #pragma unroll
        for (int n = 0; n < N_; n++) {
            int idx = neigh[m*N_ + n];
            nb[n][f] = poi[idx*E_ + f];
        }
    }
    __syncthreads();

    float accx = 0.f;
    float accn[N_];
    #pragma unroll
    for (int n = 0; n < N_; n++) accn[n] = 0.f;
    for (int e = 0; e < E_; e++) {
        float wv = wT[e*E_ + f];
        accx += nb[16][e] * wv;
        #pragma unroll
        for (int n = 0; n < N_; n++) accn[n] += nb[n][e] * wv;
    }
    px[f] = accx;
    #pragma unroll
    for (int n = 0; n < N_; n++) pn[n][f] = accn[n];
    __syncthreads();

    float epx = 0.f;
    float ea[N_];
    #pragma unroll
    for (int n = 0; n < N_; n++) ea[n] = 0.f;
    for (int c = 0; c < E_; c++) {
        float a1 = aWT[c*E_ + f];
        float a2 = aWT[(E_ + c)*E_ + f];
        epx += px[c] * a1;
        #pragma unroll
        for (int n = 0; n < N_; n++) ea[n] += pn[n][c] * a2;
    }
    float abf = ab[f];
    float mx = -1e30f;
    #pragma unroll
    for (int n = 0; n < N_; n++) {
        float ev = epx + ea[n] + abf;
        ev = (ev >= 0.f) ? ev : NEG * ev;
        ea[n] = ev;
        mx = fmaxf(mx, ev);
    }
    float s = 0.f, o = 0.f;
    #pragma unroll
    for (int n = 0; n < N_; n++) {
        float p = expf(ea[n] - mx);
        s += p;
        o += p * pn[n][f];
    }
    outbuf[m*E_ + f] = o / s;
}

// ---------------- kernel 3: LSTM preactivation (fp16 weights) ----------------
// 256 threads, 8 rows/block: cg=tid&127 -> 4 gate-cols, rh=tid>>7 -> 4 rows.
__global__ __launch_bounds__(256) void pre_kernel(const int* __restrict__ x,
                                                  const float* __restrict__ poi,
                                                  const float* __restrict__ Ub) {
    int tid = threadIdx.x;
    int cg = tid & 127;
    int rh = tid >> 7;
    int m0 = blockIdx.x * 8;
    __shared__ float xs[8][3*E_];
    for (int i = tid; i < 8*3*E_; i += 256) {
        int r = i / (3*E_), e = i % (3*E_);
        int m = m0 + r;
        float v;
        if (e < E_)        v = poi[x[m]*E_ + e];
        else if (e < 2*E_) v = g_spatial[m*E_ + (e - E_)];
        else               v = g_temporal[m*E_ + (e - 2*E_)];
        xs[r][e] = v;
    }
    __syncthreads();

    float4 ub = reinterpret_cast<const float4*>(Ub)[cg];
    float4 acc[4];
    #pragma unroll
    for (int r = 0; r < 4; r++) acc[r] = ub;

    for (int e = 0; e < E_; e++) {
        // 4 gate-cols as 2 half2 per weight array (8B uint2 loads)
        uint2 u1 = *reinterpret_cast<const uint2*>(&g_W16 [e*G4_ + 4*cg]);
        uint2 u2 = *reinterpret_cast<const uint2*>(&g_sW16[e*G4_ + 4*cg]);
        uint2 u3 = *reinterpret_cast<const uint2*>(&g_tW16[e*G4_ + 4*cg]);
        float2 w1a = __half22float2(*reinterpret_cast<__half2*>(&u1.x));
        float2 w1b = __half22float2(*reinterpret_cast<__half2*>(&u1.y));
        float2 w2a = __half22float2(*reinterpret_cast<__half2*>(&u2.x));
        float2 w2b = __half22float2(*reinterpret_cast<__half2*>(&u2.y));
        float2 w3a = __half22float2(*reinterpret_cast<__half2*>(&u3.x));
        float2 w3b = __half22float2(*reinterpret_cast<__half2*>(&u3.y));
        #pragma unroll
        for (int r = 0; r < 4; r++) {
            int row = rh*4 + r;
            float x1 = xs[row][e], x2 = xs[row][e + E_], x3 = xs[row][e + 2*E_];
            acc[r].x += x1*w1a.x + x2*w2a.x + x3*w3a.x;
            acc[r].y += x1*w1a.y + x2*w2a.y + x3*w3a.y;
            acc[r].z += x1*w1b.x + x2*w2b.x + x3*w3b.x;
            acc[r].w += x1*w1b.y + x2*w2b.y + x3*w3b.y;
        }
    }
    #pragma unroll
    for (int r = 0; r < 4; r++)
        reinterpret_cast<float4*>(g_preXST + (size_t)(m0 + rh*4 + r)*G4_)[cg] = acc[r];
}

// ---------------- kernel 4: sequential LSTM, 256 threads, fp16 U (half2 loads) --
__global__ __launch_bounds__(256) void lstm_kernel() {
    int b = blockIdx.x;
    int tid = threadIdx.x;          // handles gate-cols 2tid, 2tid+1
    __shared__ float hs[H_];
    __shared__ float gsm[G4_];
    float c = 0.f;
    if (tid < H_) hs[tid] = 0.f;
    __syncthreads();
    const __half2* U2 = reinterpret_cast<const __half2*>(g_U16);
    for (int t = 0; t < T_; t++) {
        int m = b*T_ + t;
        float2 a = reinterpret_cast<const float2*>(g_preXST + (size_t)m*G4_)[tid];
        #pragma unroll 8
        for (int e = 0; e < E_; e++) {
            float h = hs[e];
            float2 u = __half22float2(U2[e*256 + tid]);
            a.x += h*u.x; a.y += h*u.y;
        }
        gsm[2*tid]   = a.x;
        gsm[2*tid+1] = a.y;
        __syncthreads();
        if (tid < H_) {
            float ig = 1.f / (1.f + expf(-gsm[tid]));
            float fg = 1.f / (1.f + expf(-gsm[H_ + tid]));
            float og = 1.f / (1.f + expf(-gsm[2*H_ + tid]));
            float gg = tanhf(gsm[3*H_ + tid]);
            c = fg*c + ig*gg;
            float h = og * tanhf(c);
            hs[tid] = h;
            g_hout[m*H_ + tid] = h;
        }
        __syncthreads();
    }
}

// ---------------- kernel 5: concat + fp16 A ----------------
__global__ void fuse_kernel(const int* __restrict__ users, const float* __restrict__ user_table) {
    int m = blockIdx.x;
    int k = threadIdx.x;
    int u = users[m];
    float v = (k < 128) ? user_table[u*128 + k] : g_hout[m*H_ + (k - 128)];
    g_Ah[m*K_ + k] = __float2half(v);
}

// ---------------- kernel 6: head GEMM  (single-pass fp16) ----------------
// CTA tile 128x128, 8 warps (2x4), warp tile 64x32, BK=32, double-buffered cp.async.
// 8 chunks of K=32: logits = fp16(A) * fp16(B) + bias, fp32 accumulate.
#define ROWB 40              // smem row stride in uint16 units (80 bytes)
#define NKCH 8

__device__ __forceinline__ void cpa16s(uint32_t dst, const void* src) {
    asm volatile("cp.async.cg.shared.global [%0], [%1], 16;" :: "r"(dst), "l"(src));
}
__device__ __forceinline__ void ldsm4(uint32_t* r, uint32_t addr) {
    asm volatile("ldmatrix.sync.aligned.m8n8.x4.shared.b16 {%0,%1,%2,%3}, [%4];"
                 : "=r"(r[0]), "=r"(r[1]), "=r"(r[2]), "=r"(r[3]) : "r"(addr));
}
__device__ __forceinline__ void mma16816h(float* c, const uint32_t* a, uint32_t b0, uint32_t b1) {
    asm volatile("mma.sync.aligned.m16n8k16.row.col.f32.f16.f16.f32 "
                 "{%0,%1,%2,%3}, {%4,%5,%6,%7}, {%8,%9}, {%0,%1,%2,%3};"
                 : "+f"(c[0]), "+f"(c[1]), "+f"(c[2]), "+f"(c[3])
                 : "r"(a[0]), "r"(a[1]), "r"(a[2]), "r"(a[3]), "r"(b0), "r"(b1));
}

__global__ __launch_bounds__(256, 2) void gemm_mma_kernel(const float* __restrict__ bias,
                                                          float* __restrict__ out) {
    __shared__ __align__(16) uint16_t sA[2][128*ROWB];
    __shared__ __align__(16) uint16_t sB[2][128*ROWB];
    int tid = threadIdx.x;
    int wid = tid >> 5, lane = tid & 31;
    int wm = wid >> 2, wn = wid & 3;
    int m0 = blockIdx.x * 128;
    int n0 = blockIdx.y * 128;

    float acc[16][4];
    #pragma unroll
    for (int i = 0; i < 16; i++)
        #pragma unroll
        for (int q = 0; q < 4; q++) acc[i][q] = 0.f;

    uint32_t sA_u[2], sB_u[2];
    sA_u[0] = (uint32_t)__cvta_generic_to_shared(sA[0]);
    sA_u[1] = (uint32_t)__cvta_generic_to_shared(sA[1]);
    sB_u[0] = (uint32_t)__cvta_generic_to_shared(sB[0]);
    sB_u[1] = (uint32_t)__cvta_generic_to_shared(sB[1]);

    // loader: 64B per row per chunk for A(128 rows) + B(128 rows); gmem row = 512B.
    auto load_chunk = [&](int kc, int stg) {
        const char* Asrc = (const char*)g_Ah;
        const char* Bsrc = (const char*)g_Bh;
        int chb = kc * 64;
        #pragma unroll
        for (int it = 0; it < 2; it++) {
            int i = tid + it*256;          // 0..511
            int r = i >> 2, gc = i & 3;    // row, 16B granule
            uint32_t soff = (uint32_t)(r*80 + gc*16);
            cpa16s(sA_u[stg] + soff, Asrc + (size_t)(m0 + r)*512 + chb + gc*16);
            cpa16s(sB_u[stg] + soff, Bsrc + (size_t)(n0 + r)*512 + chb + gc*16);
        }
        asm volatile("cp.async.commit_group;" ::: "memory");
    };

    load_chunk(0, 0);

    int rowsel = lane & 7;
    int mat01 = (lane >> 3) & 1;
    int mat23 = (lane >> 4);

    for (int kc = 0; kc < NKCH; kc++) {
        int stg = kc & 1;
        if (kc + 1 < NKCH) {
            load_chunk(kc + 1, (kc + 1) & 1);
            asm volatile("cp.async.wait_group 1;" ::: "memory");
        } else {
            asm volatile("cp.async.wait_group 0;" ::: "memory");
        }
        __syncthreads();

        #pragma unroll
        for (int s = 0; s < 2; s++) {
            int colb = s*16 + mat23*8;
            uint32_t afr[4][4];
            #pragma unroll
            for (int im = 0; im < 4; im++) {
                int row = wm*64 + im*16 + mat01*8 + rowsel;
                ldsm4(afr[im], sA_u[stg] + (uint32_t)(row*ROWB + colb)*2u);
            }
            uint32_t bfr[2][4];
            #pragma unroll
            for (int j2 = 0; j2 < 2; j2++) {
                int row = wn*32 + j2*16 + mat01*8 + rowsel;
                ldsm4(bfr[j2], sB_u[stg] + (uint32_t)(row*ROWB + colb)*2u);
            }
            #pragma unroll
            for (int im = 0; im < 4; im++)
                #pragma unroll
                for (int jn = 0; jn < 4; jn++) {
                    int h = jn & 1;
                    mma16816h(acc[im*4 + jn], afr[im], bfr[jn>>1][h], bfr[jn>>1][h + 2]);
                }
        }
        __syncthreads();
    }

    // epilogue: c0=(g,2t) c1=(g,2t+1) c2=(g+8,2t) c3=(g+8,2t+1)
    int g = lane >> 2, t = lane & 3;
    #pragma unroll
    for (int im = 0; im < 4; im++) {
        int row = m0 + wm*64 + im*16 + g;
        size_t r0 = (size_t)row * C_;
        #pragma unroll
        for (int jn = 0; jn < 4; jn++) {
            int col = n0 + wn*32 + jn*8 + 2*t;
            if (col < C_) {
                float2 bv = *reinterpret_cast<const float2*>(bias + col);
                const float* a = acc[im*4 + jn];
                float2 v0 = make_float2(a[0] + bv.x, a[1] + bv.y);
                float2 v1 = make_float2(a[2] + bv.x, a[3] + bv.y);
                *reinterpret_cast<float2*>(out + r0 + col) = v0;
                *reinterpret_cast<float2*>(out + r0 + (size_t)8*C_ + col) = v1;
            }
        }
    }
}

// ---------------- launch ----------------
extern "C" void kernel_launch(void* const* d_in, const int* in_sizes, int n_in,
                              void* d_out, int out_size) {
    const int*   x       = (const int*)  d_in[0];
    const int*   users   = (const int*)  d_in[1];
    const int*   spn     = (const int*)  d_in[2];
    const int*   tpn     = (const int*)  d_in[3];
    const float* poi     = (const float*)d_in[4];
    const float* usert   = (const float*)d_in[5];
    const float* sp_w    = (const float*)d_in[6];
    const float* sp_aW   = (const float*)d_in[7];
    const float* sp_ab   = (const float*)d_in[8];
    const float* tp_w    = (const float*)d_in[9];
    const float* tp_aW   = (const float*)d_in[10];
    const float* tp_ab   = (const float*)d_in[11];
    const float* W       = (const float*)d_in[12];
    const float* U       = (const float*)d_in[13];
    const float* Ub      = (const float*)d_in[14];
    const float* sW      = (const float*)d_in[15];
    const float* tW      = (const float*)d_in[16];
    const float* fuseW   = (const float*)d_in[17];
    const float* fuseb   = (const float*)d_in[18];
    float* out = (float*)d_out;

    prep_kernel<<<256, 256>>>(sp_w, sp_aW, tp_w, tp_aW, W, U, sW, tW);
    convB_kernel<<<8192, 256>>>(fuseW);
    gat_kernel<<<dim3(M_, 2), 128>>>(x, spn, tpn, poi, sp_ab, tp_ab);
    pre_kernel<<<M_/8, 256>>>(x, poi, Ub);
    lstm_kernel<<<B_, 256>>>();
    fuse_kernel<<<M_, 256>>>(users, usert);
    gemm_mma_kernel<<<dim3(M_/128, CP_/128), 256>>>(fuseb, out);
}

// round 13
// speedup vs baseline: 2.3849x; 1.1435x over previous
#include <cuda_runtime.h>
#include <cuda_bf16.h>
#include <cuda_fp16.h>
#include <cstdint>

// Problem constants
#define B_  32
#define T_  64
#define M_  2048         // B*T
#define N_  16           // neighbors
#define E_  128
#define H_  128
#define G4_ 512          // 4*H
#define C_  100000
#define CP_ 100096       // padded rows = 782*128
#define K_  256          // UE + H
#define KX_ 384          // pre-GEMM K (x|spatial|temporal)
#define NEG 0.01f

// ---------------- scratch (device globals; no runtime alloc) ----------------
__device__ __align__(16) float g_spwT[E_*E_];       // [e][f]
__device__ __align__(16) float g_tpwT[E_*E_];
__device__ __align__(16) float g_spaWT[2*E_*E_];    // [c][f]
__device__ __align__(16) float g_tpaWT[2*E_*E_];
__device__ __align__(16) __half g_Wc16[G4_*KX_];    // [g][e|e|e] k-contiguous concat W,sW,tW
__device__ __align__(16) __half g_U16[E_*G4_];      // [e][g] fp16 recurrent weights
__device__ __align__(16) __half g_xs16[M_*KX_];     // [m][x_emb|spatial|temporal] fp16
__device__ __align__(16) float g_preXST[M_*G4_];
__device__ __align__(16) float g_hout[M_*H_];
// Head GEMM operands (single-pass fp16)
__device__ __align__(16) __half g_Ah[M_*K_];                  // fp16(A)
__device__ __align__(16) __half g_Bh[(size_t)CP_*K_];         // fp16(B)

// ---------------- kernel 1: weight prep ----------------
__global__ void prep_kernel(const float* __restrict__ sp_w, const float* __restrict__ sp_aW,
                            const float* __restrict__ tp_w, const float* __restrict__ tp_aW,
                            const float* __restrict__ W, const float* __restrict__ U,
                            const float* __restrict__ sW, const float* __restrict__ tW) {
    int i = blockIdx.x * blockDim.x + threadIdx.x;
    int stride = gridDim.x * blockDim.x;
    for (int j = i; j < E_*E_; j += stride) {
        int f = j >> 7, e = j & 127;
        g_spwT[e*E_ + f] = sp_w[j];
        g_tpwT[e*E_ + f] = tp_w[j];
    }
    for (int j = i; j < E_*2*E_; j += stride) {
        int f = j >> 8, c = j & 255;
        g_spaWT[c*E_ + f] = sp_aW[j];
        g_tpaWT[c*E_ + f] = tp_aW[j];
    }
    for (int j = i; j < G4_*E_; j += stride) {
        int g = j >> 7, e = j & 127;
        g_Wc16[g*KX_ + e]         = __float2half(W[j]);
        g_Wc16[g*KX_ + 128 + e]   = __float2half(sW[j]);
        g_Wc16[g*KX_ + 256 + e]   = __float2half(tW[j]);
        g_U16 [e*G4_ + g]         = __float2half(U[j]);
    }
}

// ---------------- kernel 1b: fuseW -> fp16 (padded) ----------------
__global__ void convB_kernel(const float* __restrict__ fw) {
    size_t p2 = (size_t)blockIdx.x * blockDim.x + threadIdx.x;
    size_t tot = (size_t)CP_ * K_ / 2;
    size_t stride = (size_t)gridDim.x * blockDim.x;
    for (; p2 < tot; p2 += stride) {
        size_t p = p2 * 2;
        size_t r = p >> 8;
        float2 v = make_float2(0.f, 0.f);
        if (r < C_) v = *reinterpret_cast<const float2*>(fw + p);
        __half2 h;
        h.x = __float2half(v.x);
        h.y = __float2half(v.y);
        reinterpret_cast<__half2*>(g_Bh)[p2] = h;
    }
}

// ---------------- kernel 1c: x-embedding gather -> fp16 ----------------
__global__ void emb_kernel(const int* __restrict__ x, const float* __restrict__ poi) {
    int m = blockIdx.x;
    int f = threadIdx.x;
    g_xs16[m*KX_ + f] = __float2half(poi[x[m]*E_ + f]);
}

// ---------------- kernel 2: GAT (spatial + temporal), fp16 output ----------------
__global__ void gat_kernel(const int* __restrict__ x,
                           const int* __restrict__ sp_neigh, const int* __restrict__ tp_neigh,
                           const float* __restrict__ poi,
                           const float* __restrict__ sp_ab, const float* __restrict__ tp_ab) {
    int m = blockIdx.x;
    int which = blockIdx.y;
    int f = threadIdx.x;
    const int*   neigh  = which ? tp_neigh : sp_neigh;
    const float* wT     = which ? g_tpwT   : g_spwT;
    const float* aWT    = which ? g_tpaWT  : g_spaWT;
    const float* ab     = which ? tp_ab    : sp_ab;

    __shared__ float nb[17][E_];
    __shared__ float px[E_];
    __shared__ float pn[N_][E_];

    {
        int ix = x[m];
        nb[16][f] = poi[ix*E_ + f];
        #pragma unroll
        for (int n = 0; n < N_; n++) {
            int idx = neigh[m*N_ + n];
            nb[n][f] = poi[idx*E_ + f];
        }
    }
    __syncthreads();

    float accx = 0.f;
    float accn[N_];
    #pragma unroll
    for (int n = 0; n < N_; n++) accn[n] = 0.f;
    for (int e = 0; e < E_; e++) {
        float wv = wT[e*E_ + f];
        accx += nb[16][e] * wv;
        #pragma unroll
        for (int n = 0; n < N_; n++) accn[n] += nb[n][e] * wv;
    }
    px[f] = accx;
    #pragma unroll
    for (int n = 0; n < N_; n++) pn[n][f] = accn[n];
    __syncthreads();

    float epx = 0.f;
    float ea[N_];
    #pragma unroll
    for (int n = 0; n < N_; n++) ea[n] = 0.f;
    for (int c = 0; c < E_; c++) {
        float a1 = aWT[c*E_ + f];
        float a2 = aWT[(E_ + c)*E_ + f];
        epx += px[c] * a1;
        #pragma unroll
        for (int n = 0; n < N_; n++) ea[n] += pn[n][c] * a2;
    }
    float abf = ab[f];
    float mx = -1e30f;
    #pragma unroll
    for (int n = 0; n < N_; n++) {
        float ev = epx + ea[n] + abf;
        ev = (ev >= 0.f) ? ev : NEG * ev;
        ea[n] = ev;
        mx = fmaxf(mx, ev);
    }
    float s = 0.f, o = 0.f;
    #pragma unroll
    for (int n = 0; n < N_; n++) {
        float p = expf(ea[n] - mx);
        s += p;
        o += p * pn[n][f];
    }
    g_xs16[m*KX_ + 128 + which*128 + f] = __float2half(o / s);
}

// ---------------- shared mma helpers ----------------
#define ROWB 40              // smem row stride in uint16 units (80 bytes)

__device__ __forceinline__ void cpa16s(uint32_t dst, const void* src) {
    asm volatile("cp.async.cg.shared.global [%0], [%1], 16;" :: "r"(dst), "l"(src));
}
__device__ __forceinline__ void ldsm4(uint32_t* r, uint32_t addr) {
    asm volatile("ldmatrix.sync.aligned.m8n8.x4.shared.b16 {%0,%1,%2,%3}, [%4];"
                 : "=r"(r[0]), "=r"(r[1]), "=r"(r[2]), "=r"(r[3]) : "r"(addr));
}
__device__ __forceinline__ void mma16816h(float* c, const uint32_t* a, uint32_t b0, uint32_t b1) {
    asm volatile("mma.sync.aligned.m16n8k16.row.col.f32.f16.f16.f32 "
                 "{%0,%1,%2,%3}, {%4,%5,%6,%7}, {%8,%9}, {%0,%1,%2,%3};"
                 : "+f"(c[0]), "+f"(c[1]), "+f"(c[2]), "+f"(c[3])
                 : "r"(a[0]), "r"(a[1]), "r"(a[2]), "r"(a[3]), "r"(b0), "r"(b1));
}

// ---------------- kernel 3: LSTM preactivation via mma  (2048x512x384) ----------
#define NKP 12
__global__ __launch_bounds__(256, 2) void pre_mma_kernel(const float* __restrict__ Ub) {
    __shared__ __align__(16) uint16_t sA[2][128*ROWB];
    __shared__ __align__(16) uint16_t sB[2][128*ROWB];
    int tid = threadIdx.x;
    int wid = tid >> 5, lane = tid & 31;
    int wm = wid >> 2, wn = wid & 3;
    int m0 = blockIdx.x * 128;
    int n0 = blockIdx.y * 128;

    float acc[16][4];
    #pragma unroll
    for (int i = 0; i < 16; i++)
        #pragma unroll
        for (int q = 0; q < 4; q++) acc[i][q] = 0.f;

    uint32_t sA_u[2], sB_u[2];
    sA_u[0] = (uint32_t)__cvta_generic_to_shared(sA[0]);
    sA_u[1] = (uint32_t)__cvta_generic_to_shared(sA[1]);
    sB_u[0] = (uint32_t)__cvta_generic_to_shared(sB[0]);
    sB_u[1] = (uint32_t)__cvta_generic_to_shared(sB[1]);

    auto load_chunk = [&](int kc, int stg) {
        int chb = kc * 64;
        #pragma unroll
        for (int it = 0; it < 2; it++) {
            int i = tid + it*256;
            int r = i >> 2, gc = i & 3;
            uint32_t soff = (uint32_t)(r*80 + gc*16);
            cpa16s(sA_u[stg] + soff, (const char*)g_xs16 + (size_t)(m0 + r)*768 + chb + gc*16);
            cpa16s(sB_u[stg] + soff, (const char*)g_Wc16 + (size_t)(n0 + r)*768 + chb + gc*16);
        }
        asm volatile("cp.async.commit_group;" ::: "memory");
    };

    load_chunk(0, 0);

    int rowsel = lane & 7;
    int mat01 = (lane >> 3) & 1;
    int mat23 = (lane >> 4);

    for (int kc = 0; kc < NKP; kc++) {
        int stg = kc & 1;
        if (kc + 1 < NKP) {
            load_chunk(kc + 1, (kc + 1) & 1);
            asm volatile("cp.async.wait_group 1;" ::: "memory");
        } else {
            asm volatile("cp.async.wait_group 0;" ::: "memory");
        }
        __syncthreads();

        #pragma unroll
        for (int s = 0; s < 2; s++) {
            int colb = s*16 + mat23*8;
            uint32_t afr[4][4];
            #pragma unroll
            for (int im = 0; im < 4; im++) {
                int row = wm*64 + im*16 + mat01*8 + rowsel;
                ldsm4(afr[im], sA_u[stg] + (uint32_t)(row*ROWB + colb)*2u);
            }
            uint32_t bfr[2][4];
            #pragma unroll
            for (int j2 = 0; j2 < 2; j2++) {
                int row = wn*32 + j2*16 + mat01*8 + rowsel;
                ldsm4(bfr[j2], sB_u[stg] + (uint32_t)(row*ROWB + colb)*2u);
            }
            #pragma unroll
            for (int im = 0; im < 4; im++)
                #pragma unroll
                for (int jn = 0; jn < 4; jn++) {
                    int h = jn & 1;
                    mma16816h(acc[im*4 + jn], afr[im], bfr[jn>>1][h], bfr[jn>>1][h + 2]);
                }
        }
        __syncthreads();
    }

    int g = lane >> 2, t = lane & 3;
    #pragma unroll
    for (int im = 0; im < 4; im++) {
        int row = m0 + wm*64 + im*16 + g;
        size_t r0 = (size_t)row * G4_;
        #pragma unroll
        for (int jn = 0; jn < 4; jn++) {
            int col = n0 + wn*32 + jn*8 + 2*t;
            float2 bv = *reinterpret_cast<const float2*>(Ub + col);
            const float* a = acc[im*4 + jn];
            float2 v0 = make_float2(a[0] + bv.x, a[1] + bv.y);
            float2 v1 = make_float2(a[2] + bv.x, a[3] + bv.y);
            *reinterpret_cast<float2*>(g_preXST + r0 + col) = v0;
            *reinterpret_cast<float2*>(g_preXST + r0 + (size_t)8*G4_ + col) = v1;
        }
    }
}

// ---------------- kernel 4: sequential LSTM, 512 threads, U in registers --------
// col = tid&255 handles gate-cols 2col,2col+1; eh = tid>>8 handles e-half.
__global__ __launch_bounds__(512) void lstm_kernel() {
    int b = blockIdx.x;
    int tid = threadIdx.x;
    int col = tid & 255;
    int eh = tid >> 8;
    __shared__ float hs[H_];
    __shared__ float2 psum[2][256];

    // persistent register-resident recurrent weights: 64 half2 per thread
    __half2 u[64];
    #pragma unroll
    for (int e = 0; e < 64; e++)
        u[e] = *reinterpret_cast<const __half2*>(&g_U16[(size_t)(eh*64 + e)*G4_ + 2*col]);

    float c = 0.f;
    if (tid < H_) hs[tid] = 0.f;
    __syncthreads();

    const float* P = reinterpret_cast<const float*>(psum);
    for (int t = 0; t < T_; t++) {
        int m = b*T_ + t;
        float2 p;
        if (eh == 0) p = reinterpret_cast<const float2*>(g_preXST + (size_t)m*G4_)[col];
        else         p = make_float2(0.f, 0.f);
        const float4* hs4 = reinterpret_cast<const float4*>(hs);
        #pragma unroll
        for (int e4 = 0; e4 < 16; e4++) {
            float4 hv = hs4[eh*16 + e4];
            float2 u0 = __half22float2(u[e4*4 + 0]);
            float2 u1 = __half22float2(u[e4*4 + 1]);
            float2 u2 = __half22float2(u[e4*4 + 2]);
            float2 u3 = __half22float2(u[e4*4 + 3]);
            p.x += hv.x*u0.x + hv.y*u1.x + hv.z*u2.x + hv.w*u3.x;
            p.y += hv.x*u0.y + hv.y*u1.y + hv.z*u2.y + hv.w*u3.y;
        }
        psum[eh][col] = p;
        __syncthreads();
        if (tid < H_) {
            int jc = tid >> 1, jb = tid & 1;
            // gate g: value = P[(g>>1)*2 + (g&1)] with eh-offset 512
            float a_i = P[(jc      )*2 + jb] + P[512 + (jc      )*2 + jb];
            float a_f = P[(64  + jc)*2 + jb] + P[512 + (64  + jc)*2 + jb];
            float a_o = P[(128 + jc)*2 + jb] + P[512 + (128 + jc)*2 + jb];
            float a_g = P[(192 + jc)*2 + jb] + P[512 + (192 + jc)*2 + jb];
            // NB: tid maps to gate-col pairs: gate j = 2*jc + jb = tid  (identity)
            float ig = 1.f / (1.f + expf(-a_i));
            float fg = 1.f / (1.f + expf(-a_f));
            float og = 1.f / (1.f + expf(-a_o));
            float gg = tanhf(a_g);
            c = fg*c + ig*gg;
            float h = og * tanhf(c);
            hs[tid] = h;
            g_hout[m*H_ + tid] = h;
        }
        __syncthreads();
    }
}

// ---------------- kernel 5: concat + fp16 A ----------------
__global__ void fuse_kernel(const int* __restrict__ users, const float* __restrict__ user_table) {
    int m = blockIdx.x;
    int k = threadIdx.x;
    int u = users[m];
    float v = (k < 128) ? user_table[u*128 + k] : g_hout[m*H_ + (k - 128)];
    g_Ah[m*K_ + k] = __float2half(v);
}

// ---------------- kernel 6: head GEMM  (single-pass fp16) ----------------
#define NKCH 8
__global__ __launch_bounds__(256, 2) void gemm_mma_kernel(const float* __restrict__ bias,
                                                          float* __restrict__ out) {
    __shared__ __align__(16) uint16_t sA[2][128*ROWB];
    __shared__ __align__(16) uint16_t sB[2][128*ROWB];
    int tid = threadIdx.x;
    int wid = tid >> 5, lane = tid & 31;
    int wm = wid >> 2, wn = wid & 3;
    int m0 = blockIdx.x * 128;
    int n0 = blockIdx.y * 128;

    float acc[16][4];
    #pragma unroll
    for (int i = 0; i < 16; i++)
        #pragma unroll
        for (int q = 0; q < 4; q++) acc[i][q] = 0.f;

    uint32_t sA_u[2], sB_u[2];
    sA_u[0] = (uint32_t)__cvta_generic_to_shared(sA[0]);
    sA_u[1] = (uint32_t)__cvta_generic_to_shared(sA[1]);
    sB_u[0] = (uint32_t)__cvta_generic_to_shared(sB[0]);
    sB_u[1] = (uint32_t)__cvta_generic_to_shared(sB[1]);

    auto load_chunk = [&](int kc, int stg) {
        int chb = kc * 64;
        #pragma unroll
        for (int it = 0; it < 2; it++) {
            int i = tid + it*256;
            int r = i >> 2, gc = i & 3;
            uint32_t soff = (uint32_t)(r*80 + gc*16);
            cpa16s(sA_u[stg] + soff, (const char*)g_Ah + (size_t)(m0 + r)*512 + chb + gc*16);
            cpa16s(sB_u[stg] + soff, (const char*)g_Bh + (size_t)(n0 + r)*512 + chb + gc*16);
        }
        asm volatile("cp.async.commit_group;" ::: "memory");
    };

    load_chunk(0, 0);

    int rowsel = lane & 7;
    int mat01 = (lane >> 3) & 1;
    int mat23 = (lane >> 4);

    for (int kc = 0; kc < NKCH; kc++) {
        int stg = kc & 1;
        if (kc + 1 < NKCH) {
            load_chunk(kc + 1, (kc + 1) & 1);
            asm volatile("cp.async.wait_group 1;" ::: "memory");
        } else {
            asm volatile("cp.async.wait_group 0;" ::: "memory");
        }
        __syncthreads();

        #pragma unroll
        for (int s = 0; s < 2; s++) {
            int colb = s*16 + mat23*8;
            uint32_t afr[4][4];
            #pragma unroll
            for (int im = 0; im < 4; im++) {
                int row = wm*64 + im*16 + mat01*8 + rowsel;
                ldsm4(afr[im], sA_u[stg] + (uint32_t)(row*ROWB + colb)*2u);
            }
            uint32_t bfr[2][4];
            #pragma unroll
            for (int j2 = 0; j2 < 2; j2++) {
                int row = wn*32 + j2*16 + mat01*8 + rowsel;
                ldsm4(bfr[j2], sB_u[stg] + (uint32_t)(row*ROWB + colb)*2u);
            }
            #pragma unroll
            for (int im = 0; im < 4; im++)
                #pragma unroll
                for (int jn = 0; jn < 4; jn++) {
                    int h = jn & 1;
                    mma16816h(acc[im*4 + jn], afr[im], bfr[jn>>1][h], bfr[jn>>1][h + 2]);
                }
        }
        __syncthreads();
    }

    int g = lane >> 2, t = lane & 3;
    #pragma unroll
    for (int im = 0; im < 4; im++) {
        int row = m0 + wm*64 + im*16 + g;
        size_t r0 = (size_t)row * C_;
        #pragma unroll
        for (int jn = 0; jn < 4; jn++) {
            int col = n0 + wn*32 + jn*8 + 2*t;
            if (col < C_) {
                float2 bv = *reinterpret_cast<const float2*>(bias + col);
                const float* a = acc[im*4 + jn];
                float2 v0 = make_float2(a[0] + bv.x, a[1] + bv.y);
                float2 v1 = make_float2(a[2] + bv.x, a[3] + bv.y);
                *reinterpret_cast<float2*>(out + r0 + col) = v0;
                *reinterpret_cast<float2*>(out + r0 + (size_t)8*C_ + col) = v1;
            }
        }
    }
}

// ---------------- launch ----------------
extern "C" void kernel_launch(void* const* d_in, const int* in_sizes, int n_in,
                              void* d_out, int out_size) {
    const int*   x       = (const int*)  d_in[0];
    const int*   users   = (const int*)  d_in[1];
    const int*   spn     = (const int*)  d_in[2];
    const int*   tpn     = (const int*)  d_in[3];
    const float* poi     = (const float*)d_in[4];
    const float* usert   = (const float*)d_in[5];
    const float* sp_w    = (const float*)d_in[6];
    const float* sp_aW   = (const float*)d_in[7];
    const float* sp_ab   = (const float*)d_in[8];
    const float* tp_w    = (const float*)d_in[9];
    const float* tp_aW   = (const float*)d_in[10];
    const float* tp_ab   = (const float*)d_in[11];
    const float* W       = (const float*)d_in[12];
    const float* U       = (const float*)d_in[13];
    const float* Ub      = (const float*)d_in[14];
    const float* sW      = (const float*)d_in[15];
    const float* tW      = (const float*)d_in[16];
    const float* fuseW   = (const float*)d_in[17];
    const float* fuseb   = (const float*)d_in[18];
    float* out = (float*)d_out;

    prep_kernel<<<256, 256>>>(sp_w, sp_aW, tp_w, tp_aW, W, U, sW, tW);
    convB_kernel<<<8192, 256>>>(fuseW);
    emb_kernel<<<M_, 128>>>(x, poi);
    gat_kernel<<<dim3(M_, 2), 128>>>(x, spn, tpn, poi, sp_ab, tp_ab);
    pre_mma_kernel<<<dim3(M_/128, G4_/128), 256>>>(Ub);
    lstm_kernel<<<B_, 512>>>();
    fuse_kernel<<<M_, 256>>>(users, usert);
    gemm_mma_kernel<<<dim3(M_/128, CP_/128), 256>>>(fuseb, out);
}

// round 14
// speedup vs baseline: 2.5857x; 1.0842x over previous
#include <cuda_runtime.h>
#include <cuda_bf16.h>
#include <cuda_fp16.h>
#include <cstdint>

// Problem constants
#define B_  32
#define T_  64
#define M_  2048         // B*T
#define N_  16           // neighbors
#define E_  128
#define H_  128
#define G4_ 512          // 4*H
#define C_  100000
#define CP_ 100096       // padded rows = 782*128
#define K_  256          // UE + H
#define KX_ 384          // pre-GEMM K (x|spatial|temporal)
#define NEG 0.01f

// ---------------- scratch (device globals; no runtime alloc) ----------------
__device__ __align__(16) float g_spwT[E_*E_];       // [e][f]
__device__ __align__(16) float g_tpwT[E_*E_];
__device__ __align__(16) float g_spaWT[2*E_*E_];    // [c][f]
__device__ __align__(16) float g_tpaWT[2*E_*E_];
__device__ __align__(16) __half g_Wc16[G4_*KX_];    // [g][e|e|e] k-contiguous concat W,sW,tW
__device__ __align__(16) __half g_U16[E_*G4_];      // [e][g] fp16 recurrent weights
__device__ __align__(16) __half g_xs16[M_*KX_];     // [m][x_emb|spatial|temporal] fp16
__device__ __align__(16) float g_preXST[M_*G4_];
__device__ __align__(16) float g_hout[M_*H_];
// Head GEMM operands (single-pass fp16)
__device__ __align__(16) __half g_Ah[M_*K_];                  // fp16(A)
__device__ __align__(16) __half g_Bh[(size_t)CP_*K_];         // fp16(B)

// ---------------- kernel 1: weight prep ----------------
__global__ void prep_kernel(const float* __restrict__ sp_w, const float* __restrict__ sp_aW,
                            const float* __restrict__ tp_w, const float* __restrict__ tp_aW,
                            const float* __restrict__ W, const float* __restrict__ U,
                            const float* __restrict__ sW, const float* __restrict__ tW) {
    int i = blockIdx.x * blockDim.x + threadIdx.x;
    int stride = gridDim.x * blockDim.x;
    for (int j = i; j < E_*E_; j += stride) {
        int f = j >> 7, e = j & 127;
        g_spwT[e*E_ + f] = sp_w[j];
        g_tpwT[e*E_ + f] = tp_w[j];
    }
    for (int j = i; j < E_*2*E_; j += stride) {
        int f = j >> 8, c = j & 255;
        g_spaWT[c*E_ + f] = sp_aW[j];
        g_tpaWT[c*E_ + f] = tp_aW[j];
    }
    for (int j = i; j < G4_*E_; j += stride) {
        int g = j >> 7, e = j & 127;
        g_Wc16[g*KX_ + e]         = __float2half(W[j]);
        g_Wc16[g*KX_ + 128 + e]   = __float2half(sW[j]);
        g_Wc16[g*KX_ + 256 + e]   = __float2half(tW[j]);
        g_U16 [e*G4_ + g]         = __float2half(U[j]);
    }
}

// ---------------- kernel 1b: fuseW -> fp16 (padded) ----------------
__global__ void convB_kernel(const float* __restrict__ fw) {
    size_t p2 = (size_t)blockIdx.x * blockDim.x + threadIdx.x;
    size_t tot = (size_t)CP_ * K_ / 2;
    size_t stride = (size_t)gridDim.x * blockDim.x;
    for (; p2 < tot; p2 += stride) {
        size_t p = p2 * 2;
        size_t r = p >> 8;
        float2 v = make_float2(0.f, 0.f);
        if (r < C_) v = *reinterpret_cast<const float2*>(fw + p);
        __half2 h;
        h.x = __float2half(v.x);
        h.y = __float2half(v.y);
        reinterpret_cast<__half2*>(g_Bh)[p2] = h;
    }
}

// ---------------- kernel 1c: x-embedding gather -> fp16 ----------------
__global__ void emb_kernel(const int* __restrict__ x, const float* __restrict__ poi) {
    int m = blockIdx.x;
    int f = threadIdx.x;
    g_xs16[m*KX_ + f] = __float2half(poi[x[m]*E_ + f]);
}

// ---------------- kernel 2: GAT (spatial + temporal), float4 smem reads ---------
__global__ void gat_kernel(const int* __restrict__ x,
                           const int* __restrict__ sp_neigh, const int* __restrict__ tp_neigh,
                           const float* __restrict__ poi,
                           const float* __restrict__ sp_ab, const float* __restrict__ tp_ab) {
    int m = blockIdx.x;
    int which = blockIdx.y;
    int f = threadIdx.x;
    const int*   neigh  = which ? tp_neigh : sp_neigh;
    const float* wT     = which ? g_tpwT   : g_spwT;
    const float* aWT    = which ? g_tpaWT  : g_spaWT;
    const float* ab     = which ? tp_ab    : sp_ab;

    __shared__ __align__(16) float nb[17][E_];
    __shared__ __align__(16) float px[E_];
    __shared__ __align__(16) float pn[N_][E_];

    {
        int ix = x[m];
        nb[16][f] = poi[ix*E_ + f];
        #pragma unroll
        for (int n = 0; n < N_; n++) {
            int idx = neigh[m*N_ + n];
            nb[n][f] = poi[idx*E_ + f];
        }
    }
    __syncthreads();

    // projection: one LDS.128 broadcast per 4 k-steps per node
    float accx = 0.f;
    float accn[N_];
    #pragma unroll
    for (int n = 0; n < N_; n++) accn[n] = 0.f;
    for (int e = 0; e < E_; e += 4) {
        float w0 = wT[(e+0)*E_ + f];
        float w1 = wT[(e+1)*E_ + f];
        float w2 = wT[(e+2)*E_ + f];
        float w3 = wT[(e+3)*E_ + f];
        float4 xv = *reinterpret_cast<const float4*>(&nb[16][e]);
        accx += xv.x*w0 + xv.y*w1 + xv.z*w2 + xv.w*w3;
        #pragma unroll
        for (int n = 0; n < N_; n++) {
            float4 nv = *reinterpret_cast<const float4*>(&nb[n][e]);
            accn[n] += nv.x*w0 + nv.y*w1 + nv.z*w2 + nv.w*w3;
        }
    }
    px[f] = accx;
    #pragma unroll
    for (int n = 0; n < N_; n++) pn[n][f] = accn[n];
    __syncthreads();

    // attention logits, same float4 treatment
    float epx = 0.f;
    float ea[N_];
    #pragma unroll
    for (int n = 0; n < N_; n++) ea[n] = 0.f;
    for (int c = 0; c < E_; c += 4) {
        float a10 = aWT[(c+0)*E_ + f];
        float a11 = aWT[(c+1)*E_ + f];
        float a12 = aWT[(c+2)*E_ + f];
        float a13 = aWT[(c+3)*E_ + f];
        float a20 = aWT[(E_ + c+0)*E_ + f];
        float a21 = aWT[(E_ + c+1)*E_ + f];
        float a22 = aWT[(E_ + c+2)*E_ + f];
        float a23 = aWT[(E_ + c+3)*E_ + f];
        float4 pv = *reinterpret_cast<const float4*>(&px[c]);
        epx += pv.x*a10 + pv.y*a11 + pv.z*a12 + pv.w*a13;
        #pragma unroll
        for (int n = 0; n < N_; n++) {
            float4 nv = *reinterpret_cast<const float4*>(&pn[n][c]);
            ea[n] += nv.x*a20 + nv.y*a21 + nv.z*a22 + nv.w*a23;
        }
    }
    float abf = ab[f];
    float mx = -1e30f;
    #pragma unroll
    for (int n = 0; n < N_; n++) {
        float ev = epx + ea[n] + abf;
        ev = (ev >= 0.f) ? ev : NEG * ev;
        ea[n] = ev;
        mx = fmaxf(mx, ev);
    }
    float s = 0.f, o = 0.f;
    #pragma unroll
    for (int n = 0; n < N_; n++) {
        float p = expf(ea[n] - mx);
        s += p;
        o += p * pn[n][f];
    }
    g_xs16[m*KX_ + 128 + which*128 + f] = __float2half(o / s);
}

// ---------------- shared mma helpers ----------------
#define ROWB 40              // smem row stride in uint16 units (80 bytes)

__device__ __forceinline__ void cpa16s(uint32_t dst, const void* src) {
    asm volatile("cp.async.cg.shared.global [%0], [%1], 16;" :: "r"(dst), "l"(src));
}
__device__ __forceinline__ void ldsm4(uint32_t* r, uint32_t addr) {
    asm volatile("ldmatrix.sync.aligned.m8n8.x4.shared.b16 {%0,%1,%2,%3}, [%4];"
                 : "=r"(r[0]), "=r"(r[1]), "=r"(r[2]), "=r"(r[3]) : "r"(addr));
}
__device__ __forceinline__ void mma16816h(float* c, const uint32_t* a, uint32_t b0, uint32_t b1) {
    asm volatile("mma.sync.aligned.m16n8k16.row.col.f32.f16.f16.f32 "
                 "{%0,%1,%2,%3}, {%4,%5,%6,%7}, {%8,%9}, {%0,%1,%2,%3};"
                 : "+f"(c[0]), "+f"(c[1]), "+f"(c[2]), "+f"(c[3])
                 : "r"(a[0]), "r"(a[1]), "r"(a[2]), "r"(a[3]), "r"(b0), "r"(b1));
}

// ---------------- kernel 3: LSTM preactivation via mma  (2048x512x384) ----------
#define NKP 12
__global__ __launch_bounds__(256, 2) void pre_mma_kernel(const float* __restrict__ Ub) {
    __shared__ __align__(16) uint16_t sA[2][128*ROWB];
    __shared__ __align__(16) uint16_t sB[2][128*ROWB];
    int tid = threadIdx.x;
    int wid = tid >> 5, lane = tid & 31;
    int wm = wid >> 2, wn = wid & 3;
    int m0 = blockIdx.x * 128;
    int n0 = blockIdx.y * 128;

    float acc[16][4];
    #pragma unroll
    for (int i = 0; i < 16; i++)
        #pragma unroll
        for (int q = 0; q < 4; q++) acc[i][q] = 0.f;

    uint32_t sA_u[2], sB_u[2];
    sA_u[0] = (uint32_t)__cvta_generic_to_shared(sA[0]);
    sA_u[1] = (uint32_t)__cvta_generic_to_shared(sA[1]);
    sB_u[0] = (uint32_t)__cvta_generic_to_shared(sB[0]);
    sB_u[1] = (uint32_t)__cvta_generic_to_shared(sB[1]);

    auto load_chunk = [&](int kc, int stg) {
        int chb = kc * 64;
        #pragma unroll
        for (int it = 0; it < 2; it++) {
            int i = tid + it*256;
            int r = i >> 2, gc = i & 3;
            uint32_t soff = (uint32_t)(r*80 + gc*16);
            cpa16s(sA_u[stg] + soff, (const char*)g_xs16 + (size_t)(m0 + r)*768 + chb + gc*16);
            cpa16s(sB_u[stg] + soff, (const char*)g_Wc16 + (size_t)(n0 + r)*768 + chb + gc*16);
        }
        asm volatile("cp.async.commit_group;" ::: "memory");
    };

    load_chunk(0, 0);

    int rowsel = lane & 7;
    int mat01 = (lane >> 3) & 1;
    int mat23 = (lane >> 4);

    for (int kc = 0; kc < NKP; kc++) {
        int stg = kc & 1;
        if (kc + 1 < NKP) {
            load_chunk(kc + 1, (kc + 1) & 1);
            asm volatile("cp.async.wait_group 1;" ::: "memory");
        } else {
            asm volatile("cp.async.wait_group 0;" ::: "memory");
        }
        __syncthreads();

        #pragma unroll
        for (int s = 0; s < 2; s++) {
            int colb = s*16 + mat23*8;
            uint32_t afr[4][4];
            #pragma unroll
            for (int im = 0; im < 4; im++) {
                int row = wm*64 + im*16 + mat01*8 + rowsel;
                ldsm4(afr[im], sA_u[stg] + (uint32_t)(row*ROWB + colb)*2u);
            }
            uint32_t bfr[2][4];
            #pragma unroll
            for (int j2 = 0; j2 < 2; j2++) {
                int row = wn*32 + j2*16 + mat01*8 + rowsel;
                ldsm4(bfr[j2], sB_u[stg] + (uint32_t)(row*ROWB + colb)*2u);
            }
            #pragma unroll
            for (int im = 0; im < 4; im++)
                #pragma unroll
                for (int jn = 0; jn < 4; jn++) {
                    int h = jn & 1;
                    mma16816h(acc[im*4 + jn], afr[im], bfr[jn>>1][h], bfr[jn>>1][h + 2]);
                }
        }
        __syncthreads();
    }

    int g = lane >> 2, t = lane & 3;
    #pragma unroll
    for (int im = 0; im < 4; im++) {
        int row = m0 + wm*64 + im*16 + g;
        size_t r0 = (size_t)row * G4_;
        #pragma unroll
        for (int jn = 0; jn < 4; jn++) {
            int col = n0 + wn*32 + jn*8 + 2*t;
            float2 bv = *reinterpret_cast<const float2*>(Ub + col);
            const float* a = acc[im*4 + jn];
            float2 v0 = make_float2(a[0] + bv.x, a[1] + bv.y);
            float2 v1 = make_float2(a[2] + bv.x, a[3] + bv.y);
            *reinterpret_cast<float2*>(g_preXST + r0 + col) = v0;
            *reinterpret_cast<float2*>(g_preXST + r0 + (size_t)8*G4_ + col) = v1;
        }
    }
}

// ---------------- kernel 4: sequential LSTM, 512 threads, U in registers --------
__global__ __launch_bounds__(512) void lstm_kernel() {
    int b = blockIdx.x;
    int tid = threadIdx.x;
    int col = tid & 255;
    int eh = tid >> 8;
    __shared__ float hs[H_];
    __shared__ float2 psum[2][256];

    __half2 u[64];
    #pragma unroll
    for (int e = 0; e < 64; e++)
        u[e] = *reinterpret_cast<const __half2*>(&g_U16[(size_t)(eh*64 + e)*G4_ + 2*col]);

    float c = 0.f;
    if (tid < H_) hs[tid] = 0.f;
    __syncthreads();

    const float* P = reinterpret_cast<const float*>(psum);
    for (int t = 0; t < T_; t++) {
        int m = b*T_ + t;
        float2 p;
        if (eh == 0) p = reinterpret_cast<const float2*>(g_preXST + (size_t)m*G4_)[col];
        else         p = make_float2(0.f, 0.f);
        const float4* hs4 = reinterpret_cast<const float4*>(hs);
        #pragma unroll
        for (int e4 = 0; e4 < 16; e4++) {
            float4 hv = hs4[eh*16 + e4];
            float2 u0 = __half22float2(u[e4*4 + 0]);
            float2 u1 = __half22float2(u[e4*4 + 1]);
            float2 u2 = __half22float2(u[e4*4 + 2]);
            float2 u3 = __half22float2(u[e4*4 + 3]);
            p.x += hv.x*u0.x + hv.y*u1.x + hv.z*u2.x + hv.w*u3.x;
            p.y += hv.x*u0.y + hv.y*u1.y + hv.z*u2.y + hv.w*u3.y;
        }
        psum[eh][col] = p;
        __syncthreads();
        if (tid < H_) {
            int jc = tid >> 1, jb = tid & 1;
            float a_i = P[(jc      )*2 + jb] + P[512 + (jc      )*2 + jb];
            float a_f = P[(64  + jc)*2 + jb] + P[512 + (64  + jc)*2 + jb];
            float a_o = P[(128 + jc)*2 + jb] + P[512 + (128 + jc)*2 + jb];
            float a_g = P[(192 + jc)*2 + jb] + P[512 + (192 + jc)*2 + jb];
            float ig = 1.f / (1.f + expf(-a_i));
            float fg = 1.f / (1.f + expf(-a_f));
            float og = 1.f / (1.f + expf(-a_o));
            float gg = tanhf(a_g);
            c = fg*c + ig*gg;
            float h = og * tanhf(c);
            hs[tid] = h;
            g_hout[m*H_ + tid] = h;
        }
        __syncthreads();
    }
}

// ---------------- kernel 5: concat + fp16 A ----------------
__global__ void fuse_kernel(const int* __restrict__ users, const float* __restrict__ user_table) {
    int m = blockIdx.x;
    int k = threadIdx.x;
    int u = users[m];
    float v = (k < 128) ? user_table[u*128 + k] : g_hout[m*H_ + (k - 128)];
    g_Ah[m*K_ + k] = __float2half(v);
}

// ---------------- kernel 6: head GEMM  (single-pass fp16) ----------------
#define NKCH 8
__global__ __launch_bounds__(256, 2) void gemm_mma_kernel(const float* __restrict__ bias,
                                                          float* __restrict__ out) {
    __shared__ __align__(16) uint16_t sA[2][128*ROWB];
    __shared__ __align__(16) uint16_t sB[2][128*ROWB];
    int tid = threadIdx.x;
    int wid = tid >> 5, lane = tid & 31;
    int wm = wid >> 2, wn = wid & 3;
    int m0 = blockIdx.x * 128;
    int n0 = blockIdx.y * 128;

    float acc[16][4];
    #pragma unroll
    for (int i = 0; i < 16; i++)
        #pragma unroll
        for (int q = 0; q < 4; q++) acc[i][q] = 0.f;

    uint32_t sA_u[2], sB_u[2];
    sA_u[0] = (uint32_t)__cvta_generic_to_shared(sA[0]);
    sA_u[1] = (uint32_t)__cvta_generic_to_shared(sA[1]);
    sB_u[0] = (uint32_t)__cvta_generic_to_shared(sB[0]);
    sB_u[1] = (uint32_t)__cvta_generic_to_shared(sB[1]);

    auto load_chunk = [&](int kc, int stg) {
        int chb = kc * 64;
        #pragma unroll
        for (int it = 0; it < 2; it++) {
            int i = tid + it*256;
            int r = i >> 2, gc = i & 3;
            uint32_t soff = (uint32_t)(r*80 + gc*16);
            cpa16s(sA_u[stg] + soff, (const char*)g_Ah + (size_t)(m0 + r)*512 + chb + gc*16);
            cpa16s(sB_u[stg] + soff, (const char*)g_Bh + (size_t)(n0 + r)*512 + chb + gc*16);
        }
        asm volatile("cp.async.commit_group;" ::: "memory");
    };

    load_chunk(0, 0);

    int rowsel = lane & 7;
    int mat01 = (lane >> 3) & 1;
    int mat23 = (lane >> 4);

    for (int kc = 0; kc < NKCH; kc++) {
        int stg = kc & 1;
        if (kc + 1 < NKCH) {
            load_chunk(kc + 1, (kc + 1) & 1);
            asm volatile("cp.async.wait_group 1;" ::: "memory");
        } else {
            asm volatile("cp.async.wait_group 0;" ::: "memory");
        }
        __syncthreads();

        #pragma unroll
        for (int s = 0; s < 2; s++) {
            int colb = s*16 + mat23*8;
            uint32_t afr[4][4];
            #pragma unroll
            for (int im = 0; im < 4; im++) {
                int row = wm*64 + im*16 + mat01*8 + rowsel;
                ldsm4(afr[im], sA_u[stg] + (uint32_t)(row*ROWB + colb)*2u);
            }
            uint32_t bfr[2][4];
            #pragma unroll
            for (int j2 = 0; j2 < 2; j2++) {
                int row = wn*32 + j2*16 + mat01*8 + rowsel;
                ldsm4(bfr[j2], sB_u[stg] + (uint32_t)(row*ROWB + colb)*2u);
            }
            #pragma unroll
            for (int im = 0; im < 4; im++)
                #pragma unroll
                for (int jn = 0; jn < 4; jn++) {
                    int h = jn & 1;
                    mma16816h(acc[im*4 + jn], afr[im], bfr[jn>>1][h], bfr[jn>>1][h + 2]);
                }
        }
        __syncthreads();
    }

    int g = lane >> 2, t = lane & 3;
    #pragma unroll
    for (int im = 0; im < 4; im++) {
        int row = m0 + wm*64 + im*16 + g;
        size_t r0 = (size_t)row * C_;
        #pragma unroll
        for (int jn = 0; jn < 4; jn++) {
            int col = n0 + wn*32 + jn*8 + 2*t;
            if (col < C_) {
                float2 bv = *reinterpret_cast<const float2*>(bias + col);
                const float* a = acc[im*4 + jn];
                float2 v0 = make_float2(a[0] + bv.x, a[1] + bv.y);
                float2 v1 = make_float2(a[2] + bv.x, a[3] + bv.y);
                *reinterpret_cast<float2*>(out + r0 + col) = v0;
                *reinterpret_cast<float2*>(out + r0 + (size_t)8*C_ + col) = v1;
            }
        }
    }
}

// ---------------- launch ----------------
extern "C" void kernel_launch(void* const* d_in, const int* in_sizes, int n_in,
                              void* d_out, int out_size) {
    const int*   x       = (const int*)  d_in[0];
    const int*   users   = (const int*)  d_in[1];
    const int*   spn     = (const int*)  d_in[2];
    const int*   tpn     = (const int*)  d_in[3];
    const float* poi     = (const float*)d_in[4];
    const float* usert   = (const float*)d_in[5];
    const float* sp_w    = (const float*)d_in[6];
    const float* sp_aW   = (const float*)d_in[7];
    const float* sp_ab   = (const float*)d_in[8];
    const float* tp_w    = (const float*)d_in[9];
    const float* tp_aW   = (const float*)d_in[10];
    const float* tp_ab   = (const float*)d_in[11];
    const float* W       = (const float*)d_in[12];
    const float* U       = (const float*)d_in[13];
    const float* Ub      = (const float*)d_in[14];
    const float* sW      = (const float*)d_in[15];
    const float* tW      = (const float*)d_in[16];
    const float* fuseW   = (const float*)d_in[17];
    const float* fuseb   = (const float*)d_in[18];
    float* out = (float*)d_out;

    prep_kernel<<<256, 256>>>(sp_w, sp_aW, tp_w, tp_aW, W, U, sW, tW);
    convB_kernel<<<8192, 256>>>(fuseW);
    emb_kernel<<<M_, 128>>>(x, poi);
    gat_kernel<<<dim3(M_, 2), 128>>>(x, spn, tpn, poi, sp_ab, tp_ab);
    pre_mma_kernel<<<dim3(M_/128, G4_/128), 256>>>(Ub);
    lstm_kernel<<<B_, 512>>>();
    fuse_kernel<<<M_, 256>>>(users, usert);
    gemm_mma_kernel<<<dim3(M_/128, CP_/128), 256>>>(fuseb, out);
}

// round 16
// speedup vs baseline: 3.0324x; 1.1727x over previous
#include <cuda_runtime.h>
#include <cuda_bf16.h>
#include <cuda_fp16.h>
#include <cstdint>

// Problem constants
#define B_  32
#define T_  64
#define M_  2048         // B*T
#define N_  16           // neighbors
#define E_  128
#define H_  128
#define G4_ 512          // 4*H
#define C_  100000
#define CP_ 100096       // padded rows = 782*128
#define K_  256          // UE + H
#define KX_ 384          // pre-GEMM K (x|spatial|temporal)
#define NEG 0.01f
#define NBR 17           // 16 neighbors + center
#define GROWS (2*M_*NBR) // 69632 = 544*128 gat gemm rows
#define GN_ 384          // gat gemm N: [w | w2c | w1c]

// ---------------- scratch (device globals; no runtime alloc) ----------------
__device__ __align__(16) __half g_Wc16[G4_*KX_];    // [g][e|e|e] k-contig concat W,sW,tW
__device__ __align__(16) __half g_U16[E_*G4_];      // [e][g] fp16 recurrent weights
__device__ __align__(16) __half g_xs16[M_*KX_];     // [m][x_emb|spatial|temporal] fp16
__device__ __align__(16) float g_preXST[M_*G4_];
__device__ __align__(16) float g_hout[M_*H_];
// GAT pipeline
__device__ __align__(16) __half g_gw16[2*GN_*E_];   // per-GAT B: [w | w2c | w1c], k-contig
__device__ __align__(16) __half g_nb16[(size_t)GROWS*E_];   // gathered node embeddings
__device__ __align__(16) __half g_pqr[(size_t)GROWS*GN_];   // GEMM out: P|R|Q per node
// Head GEMM operands (single-pass fp16)
__device__ __align__(16) __half g_Ah[M_*K_];                  // fp16(A)
__device__ __align__(16) __half g_Bh[(size_t)CP_*K_];         // fp16(B)

// ---------------- kernel 1: LSTM weight prep ----------------
__global__ void prep_kernel(const float* __restrict__ W, const float* __restrict__ U,
                            const float* __restrict__ sW, const float* __restrict__ tW) {
    int i = blockIdx.x * blockDim.x + threadIdx.x;
    int stride = gridDim.x * blockDim.x;
    for (int j = i; j < G4_*E_; j += stride) {
        int g = j >> 7, e = j & 127;
        g_Wc16[g*KX_ + e]         = __float2half(W[j]);
        g_Wc16[g*KX_ + 128 + e]   = __float2half(sW[j]);
        g_Wc16[g*KX_ + 256 + e]   = __float2half(tW[j]);
        g_U16 [e*G4_ + g]         = __float2half(U[j]);
    }
}

// ---------------- kernel 1b: fuseW -> fp16 (padded) ----------------
__global__ void convB_kernel(const float* __restrict__ fw) {
    size_t p2 = (size_t)blockIdx.x * blockDim.x + threadIdx.x;
    size_t tot = (size_t)CP_ * K_ / 2;
    size_t stride = (size_t)gridDim.x * blockDim.x;
    for (; p2 < tot; p2 += stride) {
        size_t p = p2 * 2;
        size_t r = p >> 8;
        float2 v = make_float2(0.f, 0.f);
        if (r < C_) v = *reinterpret_cast<const float2*>(fw + p);
        __half2 h;
        h.x = __float2half(v.x);
        h.y = __float2half(v.y);
        reinterpret_cast<__half2*>(g_Bh)[p2] = h;
    }
}

// ---------------- kernel 1c: x-embedding gather -> fp16 ----------------
__global__ void emb_kernel(const int* __restrict__ x, const float* __restrict__ poi) {
    int m = blockIdx.x;
    int f = threadIdx.x;
    g_xs16[m*KX_ + f] = __float2half(poi[x[m]*E_ + f]);
}

// ---------------- kernel 1d: GAT combined weights ----------------
// part 0: w[f][e];  part 1: w2c[f][e] = sum_c aW[f][128+c] w[c][e];
// part 2: w1c[f][e] = sum_c aW[f][c] w[c][e]
__global__ void wcomb_kernel(const float* __restrict__ sp_w, const float* __restrict__ sp_aW,
                             const float* __restrict__ tp_w, const float* __restrict__ tp_aW) {
    int e = threadIdx.x;
    int f = blockIdx.x;
    int part = blockIdx.y;
    int which = blockIdx.z;
    const float* w  = which ? tp_w  : sp_w;
    const float* aW = which ? tp_aW : sp_aW;
    float v;
    if (part == 0) {
        v = w[f*E_ + e];
    } else {
        int off = (part == 1) ? 128 : 0;
        __shared__ float arow[E_];
        arow[e] = aW[f*256 + off + e];
        __syncthreads();
        float s = 0.f;
        #pragma unroll 8
        for (int c = 0; c < E_; c++) s += arow[c] * w[c*E_ + e];
        v = s;
    }
    g_gw16[((size_t)which*GN_ + part*128 + f)*E_ + e] = __float2half(v);
}

// ---------------- kernel 2a: gather node embeddings (fp16) ----------------
__global__ void gather_kernel(const int* __restrict__ x,
                              const int* __restrict__ spn, const int* __restrict__ tpn,
                              const float* __restrict__ poi) {
    int m = blockIdx.x;
    int which = blockIdx.y;
    int f = threadIdx.x;
    const int* nn = which ? tpn : spn;
    size_t base = ((size_t)which*M_ + m)*NBR;
    #pragma unroll
    for (int n = 0; n < N_; n++) {
        int idx = nn[m*N_ + n];
        g_nb16[(base + n)*E_ + f] = __float2half(poi[idx*E_ + f]);
    }
    g_nb16[(base + N_)*E_ + f] = __float2half(poi[x[m]*E_ + f]);
}

// ---------------- shared mma helpers ----------------
#define ROWB 40              // smem row stride in uint16 units (80 bytes)

__device__ __forceinline__ void cpa16s(uint32_t dst, const void* src) {
    asm volatile("cp.async.cg.shared.global [%0], [%1], 16;" :: "r"(dst), "l"(src));
}
__device__ __forceinline__ void ldsm4(uint32_t* r, uint32_t addr) {
    asm volatile("ldmatrix.sync.aligned.m8n8.x4.shared.b16 {%0,%1,%2,%3}, [%4];"
                 : "=r"(r[0]), "=r"(r[1]), "=r"(r[2]), "=r"(r[3]) : "r"(addr));
}
__device__ __forceinline__ void mma16816h(float* c, const uint32_t* a, uint32_t b0, uint32_t b1) {
    asm volatile("mma.sync.aligned.m16n8k16.row.col.f32.f16.f16.f32 "
                 "{%0,%1,%2,%3}, {%4,%5,%6,%7}, {%8,%9}, {%0,%1,%2,%3};"
                 : "+f"(c[0]), "+f"(c[1]), "+f"(c[2]), "+f"(c[3])
                 : "r"(a[0]), "r"(a[1]), "r"(a[2]), "r"(a[3]), "r"(b0), "r"(b1));
}

// ---- generic 128x128-tile fp16 mma core (BK=32, double-buffered) ----
// Abytes/Bbytes: gmem row strides; nk: number of 64B K-chunks.
struct MmaCore {
    uint32_t sA_u[2], sB_u[2];
    int tid, wid, lane, wm, wn, rowsel, mat01, mat23;
    float acc[16][4];

    __device__ __forceinline__ void init(uint16_t (*sA)[128*ROWB], uint16_t (*sB)[128*ROWB]) {
        tid = threadIdx.x;
        wid = tid >> 5; lane = tid & 31;
        wm = wid >> 2; wn = wid & 3;
        rowsel = lane & 7;
        mat01 = (lane >> 3) & 1;
        mat23 = (lane >> 4);
        sA_u[0] = (uint32_t)__cvta_generic_to_shared(sA[0]);
        sA_u[1] = (uint32_t)__cvta_generic_to_shared(sA[1]);
        sB_u[0] = (uint32_t)__cvta_generic_to_shared(sB[0]);
        sB_u[1] = (uint32_t)__cvta_generic_to_shared(sB[1]);
        #pragma unroll
        for (int i = 0; i < 16; i++)
            #pragma unroll
            for (int q = 0; q < 4; q++) acc[i][q] = 0.f;
    }
    __device__ __forceinline__ void load_chunk(const char* Asrc, size_t Astride,
                                               const char* Bsrc, size_t Bstride,
                                               int kc, int stg) {
        int chb = kc * 64;
        #pragma unroll
        for (int it = 0; it < 2; it++) {
            int i = tid + it*256;
            int r = i >> 2, gc = i & 3;
            uint32_t soff = (uint32_t)(r*80 + gc*16);
            cpa16s(sA_u[stg] + soff, Asrc + (size_t)r*Astride + chb + gc*16);
            cpa16s(sB_u[stg] + soff, Bsrc + (size_t)r*Bstride + chb + gc*16);
        }
        asm volatile("cp.async.commit_group;" ::: "memory");
    }
    __device__ __forceinline__ void compute(int stg) {
        #pragma unroll
        for (int s = 0; s < 2; s++) {
            int colb = s*16 + mat23*8;
            uint32_t afr[4][4];
            #pragma unroll
            for (int im = 0; im < 4; im++) {
                int row = wm*64 + im*16 + mat01*8 + rowsel;
                ldsm4(afr[im], sA_u[stg] + (uint32_t)(row*ROWB + colb)*2u);
            }
            uint32_t bfr[2][4];
            #pragma unroll
            for (int j2 = 0; j2 < 2; j2++) {
                int row = wn*32 + j2*16 + mat01*8 + rowsel;
                ldsm4(bfr[j2], sB_u[stg] + (uint32_t)(row*ROWB + colb)*2u);
            }
            #pragma unroll
            for (int im = 0; im < 4; im++)
                #pragma unroll
                for (int jn = 0; jn < 4; jn++) {
                    int h = jn & 1;
                    mma16816h(acc[im*4 + jn], afr[im], bfr[jn>>1][h], bfr[jn>>1][h + 2]);
                }
        }
    }
    __device__ __forceinline__ void run(const char* Asrc, size_t Astride,
                                        const char* Bsrc, size_t Bstride, int nk) {
        load_chunk(Asrc, Astride, Bsrc, Bstride, 0, 0);
        for (int kc = 0; kc < nk; kc++) {
            int stg = kc & 1;
            if (kc + 1 < nk) {
                load_chunk(Asrc, Astride, Bsrc, Bstride, kc + 1, (kc + 1) & 1);
                asm volatile("cp.async.wait_group 1;" ::: "memory");
            } else {
                asm volatile("cp.async.wait_group 0;" ::: "memory");
            }
            __syncthreads();
            compute(stg);
            __syncthreads();
        }
    }
};

// ---------------- kernel 2b: GAT projection GEMM (69632 x 384 x 128) ------------
__global__ __launch_bounds__(256, 2) void gat_mma_kernel() {
    __shared__ __align__(16) uint16_t sA[2][128*ROWB];
    __shared__ __align__(16) uint16_t sB[2][128*ROWB];
    MmaCore mc;
    mc.init(sA, sB);
    int r0 = blockIdx.x * 128;              // global node-row
    int which = (r0 >= M_*NBR) ? 1 : 0;
    int n0 = blockIdx.y * 128;
    mc.run((const char*)g_nb16 + (size_t)r0*256, 256,
           (const char*)g_gw16 + ((size_t)which*GN_ + n0)*256, 256, 4);

    int g = mc.lane >> 2, t = mc.lane & 3;
    #pragma unroll
    for (int im = 0; im < 4; im++) {
        int row = r0 + mc.wm*64 + im*16 + g;
        size_t ro = (size_t)row * GN_;
        #pragma unroll
        for (int jn = 0; jn < 4; jn++) {
            int col = n0 + mc.wn*32 + jn*8 + 2*t;
            const float* a = mc.acc[im*4 + jn];
            *reinterpret_cast<__half2*>(g_pqr + ro + col) = __floats2half2_rn(a[0], a[1]);
            *reinterpret_cast<__half2*>(g_pqr + ro + (size_t)8*GN_ + col) = __floats2half2_rn(a[2], a[3]);
        }
    }
}

// ---------------- kernel 2c: attention softmax + weighted sum ----------------
__global__ void attn_kernel(const float* __restrict__ sp_ab, const float* __restrict__ tp_ab) {
    int m = blockIdx.x;
    int which = blockIdx.y;
    int f = threadIdx.x;
    const float* ab = which ? tp_ab : sp_ab;
    size_t base = ((size_t)which*M_ + m)*NBR;
    float q = __half2float(g_pqr[(base + N_)*GN_ + 256 + f]);
    float abf = ab[f];
    float ea[N_], pv[N_];
    float mx = -1e30f;
    #pragma unroll
    for (int n = 0; n < N_; n++) {
        float r = __half2float(g_pqr[(base + n)*GN_ + 128 + f]);
        pv[n]   = __half2float(g_pqr[(base + n)*GN_ + f]);
        float ev = q + r + abf;
        ev = (ev >= 0.f) ? ev : NEG * ev;
        ea[n] = ev;
        mx = fmaxf(mx, ev);
    }
    float s = 0.f, o = 0.f;
    #pragma unroll
    for (int n = 0; n < N_; n++) {
        float p = expf(ea[n] - mx);
        s += p;
        o += p * pv[n];
    }
    g_xs16[m*KX_ + 128 + which*128 + f] = __float2half(o / s);
}

// ---------------- kernel 3: LSTM preactivation via mma (2048x512x384) -----------
__global__ __launch_bounds__(256, 2) void pre_mma_kernel(const float* __restrict__ Ub) {
    __shared__ __align__(16) uint16_t sA[2][128*ROWB];
    __shared__ __align__(16) uint16_t sB[2][128*ROWB];
    MmaCore mc;
    mc.init(sA, sB);
    int m0 = blockIdx.x * 128;
    int n0 = blockIdx.y * 128;
    mc.run((const char*)g_xs16 + (size_t)m0*768, 768,
           (const char*)g_Wc16 + (size_t)n0*768, 768, 12);

    int g = mc.lane >> 2, t = mc.lane & 3;
    #pragma unroll
    for (int im = 0; im < 4; im++) {
        int row = m0 + mc.wm*64 + im*16 + g;
        size_t r0 = (size_t)row * G4_;
        #pragma unroll
        for (int jn = 0; jn < 4; jn++) {
            int col = n0 + mc.wn*32 + jn*8 + 2*t;
            float2 bv = *reinterpret_cast<const float2*>(Ub + col);
            const float* a = mc.acc[im*4 + jn];
            float2 v0 = make_float2(a[0] + bv.x, a[1] + bv.y);
            float2 v1 = make_float2(a[2] + bv.x, a[3] + bv.y);
            *reinterpret_cast<float2*>(g_preXST + r0 + col) = v0;
            *reinterpret_cast<float2*>(g_preXST + r0 + (size_t)8*G4_ + col) = v1;
        }
    }
}

// ---------------- kernel 4: sequential LSTM, 512 threads, U in registers --------
__global__ __launch_bounds__(512) void lstm_kernel() {
    int b = blockIdx.x;
    int tid = threadIdx.x;
    int col = tid & 255;
    int eh = tid >> 8;
    __shared__ float hs[H_];
    __shared__ float2 psum[2][256];

    __half2 u[64];
    #pragma unroll
    for (int e = 0; e < 64; e++)
        u[e] = *reinterpret_cast<const __half2*>(&g_U16[(size_t)(eh*64 + e)*G4_ + 2*col]);

    float c = 0.f;
    if (tid < H_) hs[tid] = 0.f;
    __syncthreads();

    const float* P = reinterpret_cast<const float*>(psum);
    for (int t = 0; t < T_; t++) {
        int m = b*T_ + t;
        float2 p;
        if (eh == 0) p = reinterpret_cast<const float2*>(g_preXST + (size_t)m*G4_)[col];
        else         p = make_float2(0.f, 0.f);
        const float4* hs4 = reinterpret_cast<const float4*>(hs);
        #pragma unroll
        for (int e4 = 0; e4 < 16; e4++) {
            float4 hv = hs4[eh*16 + e4];
            float2 u0 = __half22float2(u[e4*4 + 0]);
            float2 u1 = __half22float2(u[e4*4 + 1]);
            float2 u2 = __half22float2(u[e4*4 + 2]);
            float2 u3 = __half22float2(u[e4*4 + 3]);
            p.x += hv.x*u0.x + hv.y*u1.x + hv.z*u2.x + hv.w*u3.x;
            p.y += hv.x*u0.y + hv.y*u1.y + hv.z*u2.y + hv.w*u3.y;
        }
        psum[eh][col] = p;
        __syncthreads();
        if (tid < H_) {
            int jc = tid >> 1, jb = tid & 1;
            float a_i = P[(jc      )*2 + jb] + P[512 + (jc      )*2 + jb];
            float a_f = P[(64  + jc)*2 + jb] + P[512 + (64  + jc)*2 + jb];
            float a_o = P[(128 + jc)*2 + jb] + P[512 + (128 + jc)*2 + jb];
            float a_g = P[(192 + jc)*2 + jb] + P[512 + (192 + jc)*2 + jb];
            float ig = 1.f / (1.f + expf(-a_i));
            float fg = 1.f / (1.f + expf(-a_f));
            float og = 1.f / (1.f + expf(-a_o));
            float gg = tanhf(a_g);
            c = fg*c + ig*gg;
            float h = og * tanhf(c);
            hs[tid] = h;
            g_hout[m*H_ + tid] = h;
        }
        __syncthreads();
    }
}

// ---------------- kernel 5: concat + fp16 A ----------------
__global__ void fuse_kernel(const int* __restrict__ users, const float* __restrict__ user_table) {
    int m = blockIdx.x;
    int k = threadIdx.x;
    int u = users[m];
    float v = (k < 128) ? user_table[u*128 + k] : g_hout[m*H_ + (k - 128)];
    g_Ah[m*K_ + k] = __float2half(v);
}

// ---------------- kernel 6: head GEMM (single-pass fp16) ----------------
__global__ __launch_bounds__(256, 2) void gemm_mma_kernel(const float* __restrict__ bias,
                                                          float* __restrict__ out) {
    __shared__ __align__(16) uint16_t sA[2][128*ROWB];
    __shared__ __align__(16) uint16_t sB[2][128*ROWB];
    MmaCore mc;
    mc.init(sA, sB);
    int m0 = blockIdx.x * 128;
    int n0 = blockIdx.y * 128;
    mc.run((const char*)g_Ah + (size_t)m0*512, 512,
           (const char*)g_Bh + (size_t)n0*512, 512, 8);

    int g = mc.lane >> 2, t = mc.lane & 3;
    #pragma unroll
    for (int im = 0; im < 4; im++) {
        int row = m0 + mc.wm*64 + im*16 + g;
        size_t r0 = (size_t)row * C_;
        #pragma unroll
        for (int jn = 0; jn < 4; jn++) {
            int col = n0 + mc.wn*32 + jn*8 + 2*t;
            if (col < C_) {
                float2 bv = *reinterpret_cast<const float2*>(bias + col);
                const float* a = mc.acc[im*4 + jn];
                float2 v0 = make_float2(a[0] + bv.x, a[1] + bv.y);
                float2 v1 = make_float2(a[2] + bv.x, a[3] + bv.y);
                *reinterpret_cast<float2*>(out + r0 + col) = v0;
                *reinterpret_cast<float2*>(out + r0 + (size_t)8*C_ + col) = v1;
            }
        }
    }
}

// ---------------- launch ----------------
extern "C" void kernel_launch(void* const* d_in, const int* in_sizes, int n_in,
                              void* d_out, int out_size) {
    const int*   x       = (const int*)  d_in[0];
    const int*   users   = (const int*)  d_in[1];
    const int*   spn     = (const int*)  d_in[2];
    const int*   tpn     = (const int*)  d_in[3];
    const float* poi     = (const float*)d_in[4];
    const float* usert   = (const float*)d_in[5];
    const float* sp_w    = (const float*)d_in[6];
    const float* sp_aW   = (const float*)d_in[7];
    const float* sp_ab   = (const float*)d_in[8];
    const float* tp_w    = (const float*)d_in[9];
    const float* tp_aW   = (const float*)d_in[10];
    const float* tp_ab   = (const float*)d_in[11];
    const float* W       = (const float*)d_in[12];
    const float* U       = (const float*)d_in[13];
    const float* Ub      = (const float*)d_in[14];
    const float* sW      = (const float*)d_in[15];
    const float* tW      = (const float*)d_in[16];
    const float* fuseW   = (const float*)d_in[17];
    const float* fuseb   = (const float*)d_in[18];
    float* out = (float*)d_out;

    prep_kernel<<<256, 256>>>(W, U, sW, tW);
    convB_kernel<<<8192, 256>>>(fuseW);
    emb_kernel<<<M_, 128>>>(x, poi);
    wcomb_kernel<<<dim3(128, 3, 2), 128>>>(sp_w, sp_aW, tp_w, tp_aW);
    gather_kernel<<<dim3(M_, 2), 128>>>(x, spn, tpn, poi);
    gat_mma_kernel<<<dim3(GROWS/128, GN_/128), 256>>>();
    attn_kernel<<<dim3(M_, 2), 128>>>(sp_ab, tp_ab);
    pre_mma_kernel<<<dim3(M_/128, G4_/128), 256>>>(Ub);
    lstm_kernel<<<B_, 512>>>();
    fuse_kernel<<<M_, 256>>>(users, usert);
    gemm_mma_kernel<<<dim3(M_/128, CP_/128), 256>>>(fuseb, out);
}